// round 1
// baseline (speedup 1.0000x reference)
#include <cuda_runtime.h>
#include <math.h>

// Problem constants (fixed shapes for this problem)
constexpr int FIN = 256;   // input features
constexpr int HC1 = 32;    // heads1 * out_ch1 = 2*16
constexpr int C2  = 40;    // layer-2 out channels (1 head)
constexpr int NMAX = 100000;
#define NEG 0.2f

// Scratch (device globals; no allocation allowed)
__device__ __align__(16) float g_h1[NMAX * HC1];
__device__ float g_asrc1[NMAX * 2];
__device__ float g_adst1[NMAX * 2];
__device__ __align__(16) float g_accum1[NMAX * HC1];
__device__ float g_denom1[NMAX * 2];
__device__ __align__(16) float g_h2[NMAX * C2];
__device__ float g_asrc2[NMAX];
__device__ float g_adst2[NMAX];
__device__ __align__(16) float g_accum2[NMAX * C2];
__device__ float g_denom2[NMAX];

__device__ __forceinline__ void red_add_v4(float* addr, float a, float b, float c, float d) {
    asm volatile("red.global.add.v4.f32 [%0], {%1,%2,%3,%4};"
                 :: "l"(addr), "f"(a), "f"(b), "f"(c), "f"(d) : "memory");
}

// ---------------------------------------------------------------------------
// K1: h1 = x @ W1   [N,256] x [256,32] -> [N,32]
// Block tile: 64 rows x 32 cols, k chunked by 64. 48KB static smem.
// ---------------------------------------------------------------------------
__global__ void k1_gemm(const float* __restrict__ x, const float* __restrict__ W1, int N) {
    __shared__ float ws[FIN * HC1];   // 32KB
    __shared__ float xs[64 * 64];     // 16KB
    int tid = threadIdx.x;
    int row0 = blockIdx.x * 64;

    #pragma unroll
    for (int i = 0; i < (FIN * HC1) / 256; i++) ws[tid + i * 256] = W1[tid + i * 256];

    float acc00 = 0.f, acc01 = 0.f, acc02 = 0.f, acc03 = 0.f;
    float acc10 = 0.f, acc11 = 0.f, acc12 = 0.f, acc13 = 0.f;
    int r  = (tid >> 3) * 2;   // 0..62
    int cg = (tid & 7) * 4;    // 0..28

    for (int kc = 0; kc < 4; kc++) {
        __syncthreads();  // covers ws on first iter, protects xs reuse afterwards
        #pragma unroll
        for (int i = 0; i < 4; i++) {
            int idx = tid + i * 256;        // 0..1023 float4 slots
            int rr = idx >> 4;              // row 0..63
            int cc = (idx & 15) * 4;        // col 0..60
            int gr = row0 + rr;
            float4 v = (gr < N) ? *(const float4*)&x[(long long)gr * FIN + kc * 64 + cc]
                                : make_float4(0.f, 0.f, 0.f, 0.f);
            *(float4*)&xs[rr * 64 + cc] = v;
        }
        __syncthreads();
        #pragma unroll
        for (int k = 0; k < 64; k++) {
            float x0 = xs[r * 64 + k];
            float x1 = xs[(r + 1) * 64 + k];
            float4 w = *(float4*)&ws[(kc * 64 + k) * HC1 + cg];
            acc00 += x0 * w.x; acc01 += x0 * w.y; acc02 += x0 * w.z; acc03 += x0 * w.w;
            acc10 += x1 * w.x; acc11 += x1 * w.y; acc12 += x1 * w.z; acc13 += x1 * w.w;
        }
    }
    int g0 = row0 + r;
    if (g0 < N)     *(float4*)&g_h1[g0 * HC1 + cg]       = make_float4(acc00, acc01, acc02, acc03);
    if (g0 + 1 < N) *(float4*)&g_h1[(g0 + 1) * HC1 + cg] = make_float4(acc10, acc11, acc12, acc13);
}

// ---------------------------------------------------------------------------
// K1b: per-node attention logits a_src1/a_dst1 + zero accum1/denom1.
// One warp per node; lane = flat channel (h*16+c), matches att flat layout.
// ---------------------------------------------------------------------------
__global__ void k1b_att(const float* __restrict__ as1, const float* __restrict__ ad1, int N) {
    int gid = blockIdx.x * blockDim.x + threadIdx.x;
    int n = gid >> 5, lane = gid & 31;
    if (n >= N) return;
    float v  = g_h1[n * HC1 + lane];
    float ps = v * as1[lane];
    float pd = v * ad1[lane];
    #pragma unroll
    for (int o = 8; o >= 1; o >>= 1) {
        ps += __shfl_xor_sync(0xffffffffu, ps, o);
        pd += __shfl_xor_sync(0xffffffffu, pd, o);
    }
    if ((lane & 15) == 0) {
        int h = lane >> 4;
        g_asrc1[n * 2 + h] = ps;
        g_adst1[n * 2 + h] = pd;
    }
    g_accum1[n * HC1 + lane] = 0.f;
    if (lane < 2) g_denom1[n * 2 + lane] = 0.f;
}

// ---------------------------------------------------------------------------
// K2: edge pass layer 1. 8 threads/edge. Thread t handles channels 4t..4t+3,
// head h = t>>2. Edge ids >= E are self-loops.
// accum1[dst] += exp(leaky(a_src[src,h]+a_dst[dst,h])) * h1[src]; denom1[dst,h] += exp.
// ---------------------------------------------------------------------------
__global__ void k2_edge1(const int* __restrict__ ei, int E, int ET) {
    int gid = blockIdx.x * blockDim.x + threadIdx.x;
    int e = gid >> 3;
    if (e >= ET) return;
    int t = gid & 7;
    int s, d;
    if (e < E) { s = ei[e]; d = ei[E + e]; }
    else       { s = e - E; d = s; }
    int h = t >> 2;
    float a = g_asrc1[s * 2 + h] + g_adst1[d * 2 + h];
    a = (a > 0.f) ? a : NEG * a;
    float ev = expf(a);
    float4 hv = *(const float4*)&g_h1[s * HC1 + t * 4];
    red_add_v4(&g_accum1[d * HC1 + t * 4], hv.x * ev, hv.y * ev, hv.z * ev, hv.w * ev);
    if ((t & 3) == 0) atomicAdd(&g_denom1[d * 2 + h], ev);
}

// ---------------------------------------------------------------------------
// K3: per-node: hrelu = relu(accum1/denom1 + b1); h2 = hrelu @ W2 [32x40];
// a_src2/a_dst2; zero accum2/denom2. One thread per node.
// ---------------------------------------------------------------------------
__global__ void k3_node(const float* __restrict__ b1, const float* __restrict__ W2,
                        const float* __restrict__ as2, const float* __restrict__ ad2, int N) {
    __shared__ float w2s[HC1 * C2];
    __shared__ float b1s[HC1];
    __shared__ float as2s[C2], ad2s[C2];
    int tid = threadIdx.x;
    for (int i = tid; i < HC1 * C2; i += blockDim.x) w2s[i] = W2[i];
    if (tid < HC1) b1s[tid] = b1[tid];
    if (tid < C2) { as2s[tid] = as2[tid]; ad2s[tid] = ad2[tid]; }
    __syncthreads();
    int n = blockIdx.x * blockDim.x + tid;
    if (n >= N) return;
    float inv0 = 1.f / (g_denom1[n * 2]     + 1e-16f);
    float inv1 = 1.f / (g_denom1[n * 2 + 1] + 1e-16f);
    float acc[C2];
    #pragma unroll
    for (int c = 0; c < C2; c++) acc[c] = 0.f;
    for (int j = 0; j < 8; j++) {
        float4 v = *(const float4*)&g_accum1[n * HC1 + 4 * j];
        float inv = (j < 4) ? inv0 : inv1;
        float rr[4];
        rr[0] = fmaxf(v.x * inv + b1s[4 * j + 0], 0.f);
        rr[1] = fmaxf(v.y * inv + b1s[4 * j + 1], 0.f);
        rr[2] = fmaxf(v.z * inv + b1s[4 * j + 2], 0.f);
        rr[3] = fmaxf(v.w * inv + b1s[4 * j + 3], 0.f);
        #pragma unroll
        for (int q = 0; q < 4; q++) {
            int k = 4 * j + q;
            #pragma unroll
            for (int c = 0; c < C2; c++) acc[c] += rr[q] * w2s[k * C2 + c];
        }
    }
    float s2 = 0.f, d2 = 0.f;
    #pragma unroll
    for (int c = 0; c < C2; c += 4) {
        *(float4*)&g_h2[n * C2 + c]     = make_float4(acc[c], acc[c+1], acc[c+2], acc[c+3]);
        *(float4*)&g_accum2[n * C2 + c] = make_float4(0.f, 0.f, 0.f, 0.f);
        s2 += acc[c]*as2s[c] + acc[c+1]*as2s[c+1] + acc[c+2]*as2s[c+2] + acc[c+3]*as2s[c+3];
        d2 += acc[c]*ad2s[c] + acc[c+1]*ad2s[c+1] + acc[c+2]*ad2s[c+2] + acc[c+3]*ad2s[c+3];
    }
    g_asrc2[n] = s2;
    g_adst2[n] = d2;
    g_denom2[n] = 0.f;
}

// ---------------------------------------------------------------------------
// K4: edge pass layer 2. 8 threads/edge; t<8 covers c=4t..4t+3, t<2 also
// covers c=32+4t..; t==2 does denominator.
// ---------------------------------------------------------------------------
__global__ void k4_edge2(const int* __restrict__ ei, int E, int ET) {
    int gid = blockIdx.x * blockDim.x + threadIdx.x;
    int e = gid >> 3;
    if (e >= ET) return;
    int t = gid & 7;
    int s, d;
    if (e < E) { s = ei[e]; d = ei[E + e]; }
    else       { s = e - E; d = s; }
    float a = g_asrc2[s] + g_adst2[d];
    a = (a > 0.f) ? a : NEG * a;
    float ev = expf(a);
    float4 hv = *(const float4*)&g_h2[s * C2 + 4 * t];
    red_add_v4(&g_accum2[d * C2 + 4 * t], hv.x * ev, hv.y * ev, hv.z * ev, hv.w * ev);
    if (t < 2) {
        float4 h2v = *(const float4*)&g_h2[s * C2 + 32 + 4 * t];
        red_add_v4(&g_accum2[d * C2 + 32 + 4 * t], h2v.x * ev, h2v.y * ev, h2v.z * ev, h2v.w * ev);
    }
    if (t == 2) atomicAdd(&g_denom2[d], ev);
}

// ---------------------------------------------------------------------------
// K5: out = log_softmax(accum2/denom2 + b2). One warp per node;
// lane holds c=lane and (lane<8) c=lane+32.
// ---------------------------------------------------------------------------
__global__ void k5_out(const float* __restrict__ b2, float* __restrict__ out, int N) {
    int gid = blockIdx.x * blockDim.x + threadIdx.x;
    int n = gid >> 5, lane = gid & 31;
    if (n >= N) return;
    float inv = 1.f / (g_denom2[n] + 1e-16f);
    float v0 = g_accum2[n * C2 + lane] * inv + b2[lane];
    bool has1 = lane < 8;
    float v1 = has1 ? (g_accum2[n * C2 + 32 + lane] * inv + b2[32 + lane]) : -INFINITY;
    float m = fmaxf(v0, v1);
    #pragma unroll
    for (int o = 16; o >= 1; o >>= 1) m = fmaxf(m, __shfl_xor_sync(0xffffffffu, m, o));
    float ssum = expf(v0 - m) + (has1 ? expf(v1 - m) : 0.f);
    #pragma unroll
    for (int o = 16; o >= 1; o >>= 1) ssum += __shfl_xor_sync(0xffffffffu, ssum, o);
    float lse = logf(ssum);
    out[n * C2 + lane] = v0 - m - lse;
    if (has1) out[n * C2 + 32 + lane] = v1 - m - lse;
}

// ---------------------------------------------------------------------------
extern "C" void kernel_launch(void* const* d_in, const int* in_sizes, int n_in,
                              void* d_out, int out_size) {
    const float* x   = (const float*)d_in[0];
    const int*   ei  = (const int*)d_in[1];
    const float* W1  = (const float*)d_in[2];
    const float* as1 = (const float*)d_in[3];
    const float* ad1 = (const float*)d_in[4];
    const float* b1  = (const float*)d_in[5];
    const float* W2  = (const float*)d_in[6];
    const float* as2 = (const float*)d_in[7];
    const float* ad2 = (const float*)d_in[8];
    const float* b2  = (const float*)d_in[9];
    float* out = (float*)d_out;

    int N  = in_sizes[0] / FIN;
    int E  = in_sizes[1] / 2;
    int ET = E + N;

    k1_gemm<<<(N + 63) / 64, 256>>>(x, W1, N);
    k1b_att<<<(N * 32 + 255) / 256, 256>>>(as1, ad1, N);
    k2_edge1<<<((long long)ET * 8 + 255) / 256, 256>>>(ei, E, ET);
    k3_node<<<(N + 255) / 256, 256>>>(b1, W2, as2, ad2, N);
    k4_edge2<<<((long long)ET * 8 + 255) / 256, 256>>>(ei, E, ET);
    k5_out<<<(N * 32 + 255) / 256, 256>>>(b2, out, N);
}

// round 2
// speedup vs baseline: 1.1362x; 1.1362x over previous
#include <cuda_runtime.h>
#include <math.h>

constexpr int FIN = 256;
constexpr int HC1 = 32;    // heads1 * out_ch1 = 2*16
constexpr int C2  = 40;
constexpr int NMAX = 100000;
constexpr int ETMAX = 3400000;   // E + N self loops
#define NEG 0.2f

// ---------------- scratch (device globals; no allocation allowed) ----------
__device__ __align__(16) float g_h1[NMAX * HC1];
__device__ float g_asrc1[NMAX * 2];
__device__ float g_adst1[NMAX * 2];
__device__ __align__(16) float g_h1agg[NMAX * HC1];   // normalized layer-1 aggregate
__device__ __align__(16) float g_h2[NMAX * C2];
__device__ float g_asrc2[NMAX];
__device__ float g_adst2[NMAX];
__device__ __align__(16) float g_h2agg[NMAX * C2];    // normalized layer-2 aggregate
// CSR build
__device__ int g_deg[NMAX];
__device__ int g_rowstart[NMAX + 1];
__device__ int g_cursor[NMAX];
__device__ int g_partial[128];
__device__ int g_adj[ETMAX];

// ---------------------------------------------------------------------------
// K1: h1 = x @ W1   [N,256] x [256,32] -> [N,32]  (unchanged, known-good)
// ---------------------------------------------------------------------------
__global__ void k1_gemm(const float* __restrict__ x, const float* __restrict__ W1, int N) {
    __shared__ float ws[FIN * HC1];   // 32KB
    __shared__ float xs[64 * 64];     // 16KB
    int tid = threadIdx.x;
    int row0 = blockIdx.x * 64;

    #pragma unroll
    for (int i = 0; i < (FIN * HC1) / 256; i++) ws[tid + i * 256] = W1[tid + i * 256];

    float acc00 = 0.f, acc01 = 0.f, acc02 = 0.f, acc03 = 0.f;
    float acc10 = 0.f, acc11 = 0.f, acc12 = 0.f, acc13 = 0.f;
    int r  = (tid >> 3) * 2;
    int cg = (tid & 7) * 4;

    for (int kc = 0; kc < 4; kc++) {
        __syncthreads();
        #pragma unroll
        for (int i = 0; i < 4; i++) {
            int idx = tid + i * 256;
            int rr = idx >> 4;
            int cc = (idx & 15) * 4;
            int gr = row0 + rr;
            float4 v = (gr < N) ? *(const float4*)&x[(long long)gr * FIN + kc * 64 + cc]
                                : make_float4(0.f, 0.f, 0.f, 0.f);
            *(float4*)&xs[rr * 64 + cc] = v;
        }
        __syncthreads();
        #pragma unroll
        for (int k = 0; k < 64; k++) {
            float x0 = xs[r * 64 + k];
            float x1 = xs[(r + 1) * 64 + k];
            float4 w = *(float4*)&ws[(kc * 64 + k) * HC1 + cg];
            acc00 += x0 * w.x; acc01 += x0 * w.y; acc02 += x0 * w.z; acc03 += x0 * w.w;
            acc10 += x1 * w.x; acc11 += x1 * w.y; acc12 += x1 * w.z; acc13 += x1 * w.w;
        }
    }
    int g0 = row0 + r;
    if (g0 < N)     *(float4*)&g_h1[g0 * HC1 + cg]       = make_float4(acc00, acc01, acc02, acc03);
    if (g0 + 1 < N) *(float4*)&g_h1[(g0 + 1) * HC1 + cg] = make_float4(acc10, acc11, acc12, acc13);
}

// ---------------------------------------------------------------------------
// K1b: per-node attention logits (no accumulator zeroing needed anymore)
// ---------------------------------------------------------------------------
__global__ void k1b_att(const float* __restrict__ as1, const float* __restrict__ ad1, int N) {
    int gid = blockIdx.x * blockDim.x + threadIdx.x;
    int n = gid >> 5, lane = gid & 31;
    if (n >= N) return;
    float v  = g_h1[n * HC1 + lane];
    float ps = v * as1[lane];
    float pd = v * ad1[lane];
    #pragma unroll
    for (int o = 8; o >= 1; o >>= 1) {
        ps += __shfl_xor_sync(0xffffffffu, ps, o);
        pd += __shfl_xor_sync(0xffffffffu, pd, o);
    }
    if ((lane & 15) == 0) {
        int h = lane >> 4;
        g_asrc1[n * 2 + h] = ps;
        g_adst1[n * 2 + h] = pd;
    }
}

// ---------------------------------------------------------------------------
// CSR build: zero -> histogram -> scan (3 kernels) -> fill
// ---------------------------------------------------------------------------
__global__ void k_zero(int N) {
    int i = blockIdx.x * blockDim.x + threadIdx.x;
    if (i < N) g_deg[i] = 0;
}

__global__ void k_hist(const int* __restrict__ ei, int E, int ET) {
    int e = blockIdx.x * blockDim.x + threadIdx.x;
    if (e >= ET) return;
    int d = (e < E) ? ei[E + e] : (e - E);
    atomicAdd(&g_deg[d], 1);
}

__global__ void k_scanA(int N) {
    __shared__ int sd[1024];
    int tid = threadIdx.x;
    int idx = blockIdx.x * 1024 + tid;
    int v = (idx < N) ? g_deg[idx] : 0;
    sd[tid] = v;
    __syncthreads();
    #pragma unroll
    for (int off = 1; off < 1024; off <<= 1) {
        int t = (tid >= off) ? sd[tid - off] : 0;
        __syncthreads();
        sd[tid] += t;
        __syncthreads();
    }
    if (idx < N) g_rowstart[idx] = sd[tid] - v;   // block-local exclusive
    if (tid == 1023) g_partial[blockIdx.x] = sd[1023];
}

__global__ void k_scanB(int N, int nblocks) {
    __shared__ int sd[128];
    int tid = threadIdx.x;
    int v = (tid < nblocks) ? g_partial[tid] : 0;
    sd[tid] = v;
    __syncthreads();
    #pragma unroll
    for (int off = 1; off < 128; off <<= 1) {
        int t = (tid >= off) ? sd[tid - off] : 0;
        __syncthreads();
        sd[tid] += t;
        __syncthreads();
    }
    if (tid < nblocks) g_partial[tid] = sd[tid] - v;  // exclusive
    if (tid == 127) g_rowstart[N] = sd[127];          // total = ET
}

__global__ void k_scanC(int N) {
    int idx = blockIdx.x * 1024 + threadIdx.x;
    if (idx >= N) return;
    int rs = g_rowstart[idx] + g_partial[blockIdx.x];
    g_rowstart[idx] = rs;
    g_cursor[idx] = rs;
}

__global__ void k_fill(const int* __restrict__ ei, int E, int ET) {
    int e = blockIdx.x * blockDim.x + threadIdx.x;
    if (e >= ET) return;
    int s, d;
    if (e < E) { s = ei[e]; d = ei[E + e]; }
    else       { s = e - E; d = s; }
    int pos = atomicAdd(&g_cursor[d], 1);
    g_adj[pos] = s;
}

// ---------------------------------------------------------------------------
// K2: layer-1 aggregation, gather form. One warp per dst node; lane = channel.
// Writes normalized aggregate directly (softmax denominator folded in).
// ---------------------------------------------------------------------------
__global__ void k2_gather(int N) {
    int gid = blockIdx.x * blockDim.x + threadIdx.x;
    int n = gid >> 5, lane = gid & 31;
    if (n >= N) return;
    int h = lane >> 4;
    float adstv = g_adst1[2 * n + h];
    int i = g_rowstart[n], end = g_rowstart[n + 1];
    float acc = 0.f, evs = 0.f;
    for (; i + 1 < end; i += 2) {
        int s0 = g_adj[i], s1 = g_adj[i + 1];
        float a0 = g_asrc1[2 * s0 + h] + adstv;
        float a1 = g_asrc1[2 * s1 + h] + adstv;
        a0 = (a0 > 0.f) ? a0 : NEG * a0;
        a1 = (a1 > 0.f) ? a1 : NEG * a1;
        float e0 = __expf(a0), e1 = __expf(a1);
        float v0 = g_h1[s0 * HC1 + lane];
        float v1 = g_h1[s1 * HC1 + lane];
        acc += e0 * v0;
        acc += e1 * v1;
        evs += e0 + e1;
    }
    if (i < end) {
        int s0 = g_adj[i];
        float a0 = g_asrc1[2 * s0 + h] + adstv;
        a0 = (a0 > 0.f) ? a0 : NEG * a0;
        float e0 = __expf(a0);
        acc += e0 * g_h1[s0 * HC1 + lane];
        evs += e0;
    }
    g_h1agg[n * HC1 + lane] = acc / (evs + 1e-16f);
}

// ---------------------------------------------------------------------------
// K3: per-node relu(h1agg+b1) @ W2 [32x40] -> h2, plus layer-2 logits.
// Coalesced smem staging; one thread per node computes 40 outputs.
// ---------------------------------------------------------------------------
__global__ void k3_node(const float* __restrict__ b1, const float* __restrict__ W2,
                        const float* __restrict__ as2, const float* __restrict__ ad2, int N) {
    __shared__ float w2s[HC1 * C2];
    __shared__ float b1s[HC1];
    __shared__ float as2s[C2], ad2s[C2];
    __shared__ float hs[256 * 33];
    int tid = threadIdx.x;
    int node0 = blockIdx.x * 256;
    for (int i = tid; i < HC1 * C2; i += 256) w2s[i] = W2[i];
    if (tid < HC1) b1s[tid] = b1[tid];
    if (tid < C2) { as2s[tid] = as2[tid]; ad2s[tid] = ad2[tid]; }
    __syncthreads();   // b1s ready before staging uses it

    int nmax = N - node0; if (nmax > 256) nmax = 256;
    for (int i = tid; i < 256 * 32; i += 256) {
        int nn = i >> 5, cc = i & 31;
        float v = (nn < nmax) ? g_h1agg[(node0 + nn) * HC1 + cc] : 0.f;
        hs[nn * 33 + cc] = fmaxf(v + b1s[cc], 0.f);
    }
    __syncthreads();

    if (tid >= nmax) return;
    int n = node0 + tid;
    float acc[C2];
    #pragma unroll
    for (int c = 0; c < C2; c++) acc[c] = 0.f;
    #pragma unroll
    for (int k = 0; k < HC1; k++) {
        float r = hs[tid * 33 + k];
        #pragma unroll
        for (int c = 0; c < C2; c++) acc[c] += r * w2s[k * C2 + c];
    }
    float s2 = 0.f, d2 = 0.f;
    #pragma unroll
    for (int c = 0; c < C2; c += 4) {
        *(float4*)&g_h2[n * C2 + c] = make_float4(acc[c], acc[c+1], acc[c+2], acc[c+3]);
        s2 += acc[c]*as2s[c] + acc[c+1]*as2s[c+1] + acc[c+2]*as2s[c+2] + acc[c+3]*as2s[c+3];
        d2 += acc[c]*ad2s[c] + acc[c+1]*ad2s[c+1] + acc[c+2]*ad2s[c+2] + acc[c+3]*ad2s[c+3];
    }
    g_asrc2[n] = s2;
    g_adst2[n] = d2;
}

// ---------------------------------------------------------------------------
// K4: layer-2 aggregation, gather form. One warp per dst node.
// lane covers channel lane; lanes 0..7 also cover 32+lane.
// ---------------------------------------------------------------------------
__global__ void k4_gather(int N) {
    int gid = blockIdx.x * blockDim.x + threadIdx.x;
    int n = gid >> 5, lane = gid & 31;
    if (n >= N) return;
    float adstv = g_adst2[n];
    int i = g_rowstart[n], end = g_rowstart[n + 1];
    bool extra = lane < 8;
    float acc0 = 0.f, acc1 = 0.f, evs = 0.f;
    for (; i + 1 < end; i += 2) {
        int s0 = g_adj[i], s1 = g_adj[i + 1];
        float a0 = g_asrc2[s0] + adstv;
        float a1 = g_asrc2[s1] + adstv;
        a0 = (a0 > 0.f) ? a0 : NEG * a0;
        a1 = (a1 > 0.f) ? a1 : NEG * a1;
        float e0 = __expf(a0), e1 = __expf(a1);
        acc0 += e0 * g_h2[s0 * C2 + lane];
        acc0 += e1 * g_h2[s1 * C2 + lane];
        if (extra) {
            acc1 += e0 * g_h2[s0 * C2 + 32 + lane];
            acc1 += e1 * g_h2[s1 * C2 + 32 + lane];
        }
        evs += e0 + e1;
    }
    if (i < end) {
        int s0 = g_adj[i];
        float a0 = g_asrc2[s0] + adstv;
        a0 = (a0 > 0.f) ? a0 : NEG * a0;
        float e0 = __expf(a0);
        acc0 += e0 * g_h2[s0 * C2 + lane];
        if (extra) acc1 += e0 * g_h2[s0 * C2 + 32 + lane];
        evs += e0;
    }
    float inv = 1.f / (evs + 1e-16f);
    g_h2agg[n * C2 + lane] = acc0 * inv;
    if (extra) g_h2agg[n * C2 + 32 + lane] = acc1 * inv;
}

// ---------------------------------------------------------------------------
// K5: out = log_softmax(h2agg + b2). One warp per node.
// ---------------------------------------------------------------------------
__global__ void k5_out(const float* __restrict__ b2, float* __restrict__ out, int N) {
    int gid = blockIdx.x * blockDim.x + threadIdx.x;
    int n = gid >> 5, lane = gid & 31;
    if (n >= N) return;
    float v0 = g_h2agg[n * C2 + lane] + b2[lane];
    bool has1 = lane < 8;
    float v1 = has1 ? (g_h2agg[n * C2 + 32 + lane] + b2[32 + lane]) : -INFINITY;
    float m = fmaxf(v0, v1);
    #pragma unroll
    for (int o = 16; o >= 1; o >>= 1) m = fmaxf(m, __shfl_xor_sync(0xffffffffu, m, o));
    float ssum = expf(v0 - m) + (has1 ? expf(v1 - m) : 0.f);
    #pragma unroll
    for (int o = 16; o >= 1; o >>= 1) ssum += __shfl_xor_sync(0xffffffffu, ssum, o);
    float lse = logf(ssum);
    out[n * C2 + lane] = v0 - m - lse;
    if (has1) out[n * C2 + 32 + lane] = v1 - m - lse;
}

// ---------------------------------------------------------------------------
extern "C" void kernel_launch(void* const* d_in, const int* in_sizes, int n_in,
                              void* d_out, int out_size) {
    const float* x   = (const float*)d_in[0];
    const int*   ei  = (const int*)d_in[1];
    const float* W1  = (const float*)d_in[2];
    const float* as1 = (const float*)d_in[3];
    const float* ad1 = (const float*)d_in[4];
    const float* b1  = (const float*)d_in[5];
    const float* W2  = (const float*)d_in[6];
    const float* as2 = (const float*)d_in[7];
    const float* ad2 = (const float*)d_in[8];
    const float* b2  = (const float*)d_in[9];
    float* out = (float*)d_out;

    int N  = in_sizes[0] / FIN;
    int E  = in_sizes[1] / 2;
    int ET = E + N;
    int nScanBlocks = (N + 1023) / 1024;

    k1_gemm<<<(N + 63) / 64, 256>>>(x, W1, N);
    k1b_att<<<(N * 32 + 255) / 256, 256>>>(as1, ad1, N);

    k_zero<<<(N + 255) / 256, 256>>>(N);
    k_hist<<<(ET + 255) / 256, 256>>>(ei, E, ET);
    k_scanA<<<nScanBlocks, 1024>>>(N);
    k_scanB<<<1, 128>>>(N, nScanBlocks);
    k_scanC<<<nScanBlocks, 1024>>>(N);
    k_fill<<<(ET + 255) / 256, 256>>>(ei, E, ET);

    k2_gather<<<(N * 32 + 255) / 256, 256>>>(N);
    k3_node<<<(N + 255) / 256, 256>>>(b1, W2, as2, ad2, N);
    k4_gather<<<(N * 32 + 255) / 256, 256>>>(N);
    k5_out<<<(N * 32 + 255) / 256, 256>>>(b2, out, N);
}

// round 3
// speedup vs baseline: 1.2019x; 1.0578x over previous
#include <cuda_runtime.h>
#include <math.h>

constexpr int FIN = 256;
constexpr int HC1 = 32;    // heads1 * out_ch1 = 2*16
constexpr int C2  = 40;
constexpr int NMAX = 100000;
constexpr int ETMAX = 3400000;   // E + N self loops
#define NEG 0.2f

// ---------------- scratch (device globals) ----------------
__device__ __align__(16) float g_h1[NMAX * HC1];
__device__ float g_asrc1[NMAX * 2];
__device__ float g_adst1[NMAX * 2];
__device__ __align__(16) float g_h1agg[NMAX * HC1];   // relu(agg + b1)
__device__ __align__(16) float g_h2[NMAX * C2];
__device__ float g_asrc2[NMAX];
__device__ float g_adst2[NMAX];
__device__ int g_deg[NMAX];
__device__ int g_rowstart[NMAX + 1];
__device__ int g_cursor[NMAX];
__device__ int g_partial[128];
__device__ int g_adj[ETMAX];

__device__ __forceinline__ void ffma2(unsigned long long& d, unsigned long long a, unsigned long long b) {
    asm("fma.rn.f32x2 %0, %1, %2, %0;" : "+l"(d) : "l"(a), "l"(b));
}

// ---------------------------------------------------------------------------
// K1: h1 = x @ W1 with f32x2 packed FMA; fused att-logit epilogue + deg init.
// Tile: 128 rows x 32 cols, 256 threads, thread = 4 rows x 4 cols.
// ---------------------------------------------------------------------------
__global__ __launch_bounds__(256) void k1_gemm(
    const float* __restrict__ x, const float* __restrict__ W1,
    const float* __restrict__ as1v, const float* __restrict__ ad1v, int N) {
    __shared__ float2 xs2[128 * 33];   // duplicated x: {v,v}, padded stride 33
    __shared__ float wsc[32 * 32];     // per-k-chunk slice of W1
    int tid = threadIdx.x;
    int node0 = blockIdx.x * 128;

    if (tid < 128 && node0 + tid < N) g_deg[node0 + tid] = 1;  // self loop

    unsigned long long acc[4][2];
    #pragma unroll
    for (int j = 0; j < 4; j++) { acc[j][0] = 0ull; acc[j][1] = 0ull; }
    int r  = (tid >> 3) * 4;   // 0..124
    int cg = (tid & 7) * 4;    // 0..28

    for (int kc = 0; kc < 8; kc++) {
        __syncthreads();
        // stage W chunk [32k x 32c]
        #pragma unroll
        for (int i = 0; i < 4; i++) wsc[tid + i * 256] = W1[kc * 32 * HC1 + tid + i * 256];
        // stage x chunk duplicated
        #pragma unroll
        for (int i = 0; i < 16; i++) {
            int idx = tid + i * 256;       // 0..4095
            int rr = idx >> 5, cc = idx & 31;
            int gr = node0 + rr;
            float v = (gr < N) ? x[(long long)gr * FIN + kc * 32 + cc] : 0.f;
            xs2[rr * 33 + cc] = make_float2(v, v);
        }
        __syncthreads();
        #pragma unroll
        for (int k = 0; k < 32; k++) {
            unsigned long long w01 = *(const unsigned long long*)&wsc[k * 32 + cg];
            unsigned long long w23 = *(const unsigned long long*)&wsc[k * 32 + cg + 2];
            #pragma unroll
            for (int j = 0; j < 4; j++) {
                unsigned long long xv = *(const unsigned long long*)&xs2[(r + j) * 33 + k];
                ffma2(acc[j][0], xv, w01);
                ffma2(acc[j][1], xv, w23);
            }
        }
    }

    // epilogue: write h1 + fused attention logits
    float a0 = as1v[cg], a1 = as1v[cg + 1], a2 = as1v[cg + 2], a3 = as1v[cg + 3];
    float d0 = ad1v[cg], d1 = ad1v[cg + 1], d2 = ad1v[cg + 2], d3 = ad1v[cg + 3];
    int sub = tid & 7;
    #pragma unroll
    for (int j = 0; j < 4; j++) {
        float c0 = __uint_as_float((unsigned)acc[j][0]);
        float c1 = __uint_as_float((unsigned)(acc[j][0] >> 32));
        float c2 = __uint_as_float((unsigned)acc[j][1]);
        float c3 = __uint_as_float((unsigned)(acc[j][1] >> 32));
        int gr = node0 + r + j;
        float ps = c0 * a0 + c1 * a1 + c2 * a2 + c3 * a3;
        float pd = c0 * d0 + c1 * d1 + c2 * d2 + c3 * d3;
        // reduce within 4-lane halves of each 8-lane col-group (head split)
        ps += __shfl_xor_sync(0xffffffffu, ps, 1);
        pd += __shfl_xor_sync(0xffffffffu, pd, 1);
        ps += __shfl_xor_sync(0xffffffffu, ps, 2);
        pd += __shfl_xor_sync(0xffffffffu, pd, 2);
        if (gr < N) {
            *(float4*)&g_h1[gr * HC1 + cg] = make_float4(c0, c1, c2, c3);
            if (sub == 0)      { g_asrc1[2 * gr]     = ps; g_adst1[2 * gr]     = pd; }
            else if (sub == 4) { g_asrc1[2 * gr + 1] = ps; g_adst1[2 * gr + 1] = pd; }
        }
    }
}

// ---------------------------------------------------------------------------
// CSR build
// ---------------------------------------------------------------------------
__global__ void k_hist(const int* __restrict__ ei, int E, int vec) {
    int gid = blockIdx.x * blockDim.x + threadIdx.x;
    int e4 = gid * 4;
    if (e4 >= E) return;
    if (vec && e4 + 4 <= E) {
        int4 d = *(const int4*)&ei[E + e4];
        atomicAdd(&g_deg[d.x], 1);
        atomicAdd(&g_deg[d.y], 1);
        atomicAdd(&g_deg[d.z], 1);
        atomicAdd(&g_deg[d.w], 1);
    } else {
        for (int e = e4; e < E && e < e4 + 4; e++) atomicAdd(&g_deg[ei[E + e]], 1);
    }
}

__global__ void k_scanA(int N) {
    __shared__ int sd[1024];
    int tid = threadIdx.x;
    int idx = blockIdx.x * 1024 + tid;
    int v = (idx < N) ? g_deg[idx] : 0;
    sd[tid] = v;
    __syncthreads();
    #pragma unroll
    for (int off = 1; off < 1024; off <<= 1) {
        int t = (tid >= off) ? sd[tid - off] : 0;
        __syncthreads();
        sd[tid] += t;
        __syncthreads();
    }
    if (idx < N) g_rowstart[idx] = sd[tid] - v;
    if (tid == 1023) g_partial[blockIdx.x] = sd[1023];
}

__global__ void k_scanB(int N, int nblocks) {
    __shared__ int sd[128];
    int tid = threadIdx.x;
    int v = (tid < nblocks) ? g_partial[tid] : 0;
    sd[tid] = v;
    __syncthreads();
    #pragma unroll
    for (int off = 1; off < 128; off <<= 1) {
        int t = (tid >= off) ? sd[tid - off] : 0;
        __syncthreads();
        sd[tid] += t;
        __syncthreads();
    }
    if (tid < nblocks) g_partial[tid] = sd[tid] - v;
    if (tid == 127) g_rowstart[N] = sd[127];
}

__global__ void k_scanC(int N) {
    int idx = blockIdx.x * 1024 + threadIdx.x;
    if (idx >= N) return;
    int rs = g_rowstart[idx] + g_partial[blockIdx.x];
    g_rowstart[idx] = rs;
    g_adj[rs] = idx;        // self loop occupies first slot
    g_cursor[idx] = rs + 1;
}

__global__ void k_fill(const int* __restrict__ ei, int E, int vec) {
    int gid = blockIdx.x * blockDim.x + threadIdx.x;
    int e4 = gid * 4;
    if (e4 >= E) return;
    if (vec && e4 + 4 <= E) {
        int4 s = *(const int4*)&ei[e4];
        int4 d = *(const int4*)&ei[E + e4];
        g_adj[atomicAdd(&g_cursor[d.x], 1)] = s.x;
        g_adj[atomicAdd(&g_cursor[d.y], 1)] = s.y;
        g_adj[atomicAdd(&g_cursor[d.z], 1)] = s.z;
        g_adj[atomicAdd(&g_cursor[d.w], 1)] = s.w;
    } else {
        for (int e = e4; e < E && e < e4 + 4; e++)
            g_adj[atomicAdd(&g_cursor[ei[E + e]], 1)] = ei[e];
    }
}

// ---------------------------------------------------------------------------
// K2: layer-1 aggregation (gather), unroll 4. One warp per dst node.
// Writes relu(agg + b1) directly.
// ---------------------------------------------------------------------------
__global__ void k2_gather(const float* __restrict__ b1, int N) {
    int gid = blockIdx.x * blockDim.x + threadIdx.x;
    int n = gid >> 5, lane = gid & 31;
    if (n >= N) return;
    int h = lane >> 4;
    float adstv = g_adst1[2 * n + h];
    int i = g_rowstart[n], end = g_rowstart[n + 1];
    float acc = 0.f, evs = 0.f;
    for (; i + 4 <= end; i += 4) {
        int s0 = g_adj[i], s1 = g_adj[i + 1], s2 = g_adj[i + 2], s3 = g_adj[i + 3];
        float l0 = g_asrc1[2 * s0 + h];
        float l1 = g_asrc1[2 * s1 + h];
        float l2 = g_asrc1[2 * s2 + h];
        float l3 = g_asrc1[2 * s3 + h];
        float v0 = g_h1[s0 * HC1 + lane];
        float v1 = g_h1[s1 * HC1 + lane];
        float v2 = g_h1[s2 * HC1 + lane];
        float v3 = g_h1[s3 * HC1 + lane];
        float a0 = l0 + adstv; a0 = (a0 > 0.f) ? a0 : NEG * a0;
        float a1 = l1 + adstv; a1 = (a1 > 0.f) ? a1 : NEG * a1;
        float a2 = l2 + adstv; a2 = (a2 > 0.f) ? a2 : NEG * a2;
        float a3 = l3 + adstv; a3 = (a3 > 0.f) ? a3 : NEG * a3;
        float e0 = __expf(a0), e1 = __expf(a1), e2 = __expf(a2), e3 = __expf(a3);
        acc += e0 * v0 + e1 * v1 + e2 * v2 + e3 * v3;
        evs += (e0 + e1) + (e2 + e3);
    }
    for (; i < end; i++) {
        int s0 = g_adj[i];
        float a0 = g_asrc1[2 * s0 + h] + adstv;
        a0 = (a0 > 0.f) ? a0 : NEG * a0;
        float e0 = __expf(a0);
        acc += e0 * g_h1[s0 * HC1 + lane];
        evs += e0;
    }
    g_h1agg[n * HC1 + lane] = fmaxf(acc / (evs + 1e-16f) + b1[lane], 0.f);
}

// ---------------------------------------------------------------------------
// K3: h2 = h1agg @ W2 [32x40] + layer-2 logits. Coalesced smem staging.
// ---------------------------------------------------------------------------
__global__ __launch_bounds__(256) void k3_node(
    const float* __restrict__ W2,
    const float* __restrict__ as2, const float* __restrict__ ad2, int N) {
    __shared__ float w2s[HC1 * C2];
    __shared__ float as2s[C2], ad2s[C2];
    __shared__ float hs[256 * 33];
    int tid = threadIdx.x;
    int node0 = blockIdx.x * 256;
    for (int i = tid; i < HC1 * C2; i += 256) w2s[i] = W2[i];
    if (tid < C2) { as2s[tid] = as2[tid]; ad2s[tid] = ad2[tid]; }

    int nmax = N - node0; if (nmax > 256) nmax = 256;
    for (int i = tid; i < 256 * 32; i += 256) {
        int nn = i >> 5, cc = i & 31;
        hs[nn * 33 + cc] = (nn < nmax) ? g_h1agg[(node0 + nn) * HC1 + cc] : 0.f;
    }
    __syncthreads();

    if (tid >= nmax) return;
    int n = node0 + tid;
    float acc[C2];
    #pragma unroll
    for (int c = 0; c < C2; c++) acc[c] = 0.f;
    #pragma unroll
    for (int k = 0; k < HC1; k++) {
        float rv = hs[tid * 33 + k];
        #pragma unroll
        for (int c = 0; c < C2; c++) acc[c] += rv * w2s[k * C2 + c];
    }
    float s2 = 0.f, d2 = 0.f;
    #pragma unroll
    for (int c = 0; c < C2; c += 4) {
        *(float4*)&g_h2[n * C2 + c] = make_float4(acc[c], acc[c+1], acc[c+2], acc[c+3]);
        s2 += acc[c]*as2s[c] + acc[c+1]*as2s[c+1] + acc[c+2]*as2s[c+2] + acc[c+3]*as2s[c+3];
        d2 += acc[c]*ad2s[c] + acc[c+1]*ad2s[c+1] + acc[c+2]*ad2s[c+2] + acc[c+3]*ad2s[c+3];
    }
    g_asrc2[n] = s2;
    g_adst2[n] = d2;
}

// ---------------------------------------------------------------------------
// K45: layer-2 aggregation + fused log_softmax. One warp per dst node.
// ---------------------------------------------------------------------------
__global__ void k45_gather_out(const float* __restrict__ b2, float* __restrict__ out, int N) {
    int gid = blockIdx.x * blockDim.x + threadIdx.x;
    int n = gid >> 5, lane = gid & 31;
    if (n >= N) return;
    float adstv = g_adst2[n];
    int i = g_rowstart[n], end = g_rowstart[n + 1];
    bool extra = lane < 8;
    float acc0 = 0.f, acc1 = 0.f, evs = 0.f;
    for (; i + 4 <= end; i += 4) {
        int s0 = g_adj[i], s1 = g_adj[i + 1], s2 = g_adj[i + 2], s3 = g_adj[i + 3];
        float l0 = g_asrc2[s0], l1 = g_asrc2[s1], l2 = g_asrc2[s2], l3 = g_asrc2[s3];
        float v0 = g_h2[s0 * C2 + lane];
        float v1 = g_h2[s1 * C2 + lane];
        float v2 = g_h2[s2 * C2 + lane];
        float v3 = g_h2[s3 * C2 + lane];
        float u0 = 0.f, u1 = 0.f, u2 = 0.f, u3 = 0.f;
        if (extra) {
            u0 = g_h2[s0 * C2 + 32 + lane];
            u1 = g_h2[s1 * C2 + 32 + lane];
            u2 = g_h2[s2 * C2 + 32 + lane];
            u3 = g_h2[s3 * C2 + 32 + lane];
        }
        float a0 = l0 + adstv; a0 = (a0 > 0.f) ? a0 : NEG * a0;
        float a1 = l1 + adstv; a1 = (a1 > 0.f) ? a1 : NEG * a1;
        float a2 = l2 + adstv; a2 = (a2 > 0.f) ? a2 : NEG * a2;
        float a3 = l3 + adstv; a3 = (a3 > 0.f) ? a3 : NEG * a3;
        float e0 = __expf(a0), e1 = __expf(a1), e2 = __expf(a2), e3 = __expf(a3);
        acc0 += e0 * v0 + e1 * v1 + e2 * v2 + e3 * v3;
        acc1 += e0 * u0 + e1 * u1 + e2 * u2 + e3 * u3;
        evs += (e0 + e1) + (e2 + e3);
    }
    for (; i < end; i++) {
        int s0 = g_adj[i];
        float a0 = g_asrc2[s0] + adstv;
        a0 = (a0 > 0.f) ? a0 : NEG * a0;
        float e0 = __expf(a0);
        acc0 += e0 * g_h2[s0 * C2 + lane];
        if (extra) acc1 += e0 * g_h2[s0 * C2 + 32 + lane];
        evs += e0;
    }
    float inv = 1.f / (evs + 1e-16f);
    float v0 = acc0 * inv + b2[lane];
    float v1 = extra ? (acc1 * inv + b2[32 + lane]) : -INFINITY;
    float m = fmaxf(v0, v1);
    #pragma unroll
    for (int o = 16; o >= 1; o >>= 1) m = fmaxf(m, __shfl_xor_sync(0xffffffffu, m, o));
    float ssum = expf(v0 - m) + (extra ? expf(v1 - m) : 0.f);
    #pragma unroll
    for (int o = 16; o >= 1; o >>= 1) ssum += __shfl_xor_sync(0xffffffffu, ssum, o);
    float lse = logf(ssum);
    out[n * C2 + lane] = v0 - m - lse;
    if (extra) out[n * C2 + 32 + lane] = v1 - m - lse;
}

// ---------------------------------------------------------------------------
extern "C" void kernel_launch(void* const* d_in, const int* in_sizes, int n_in,
                              void* d_out, int out_size) {
    const float* x   = (const float*)d_in[0];
    const int*   ei  = (const int*)d_in[1];
    const float* W1  = (const float*)d_in[2];
    const float* as1 = (const float*)d_in[3];
    const float* ad1 = (const float*)d_in[4];
    const float* b1  = (const float*)d_in[5];
    const float* W2  = (const float*)d_in[6];
    const float* as2 = (const float*)d_in[7];
    const float* ad2 = (const float*)d_in[8];
    const float* b2  = (const float*)d_in[9];
    float* out = (float*)d_out;

    int N  = in_sizes[0] / FIN;
    int E  = in_sizes[1] / 2;
    int vec = ((E & 3) == 0) ? 1 : 0;
    int nScanBlocks = (N + 1023) / 1024;
    int eThreads = (E + 3) / 4;

    k1_gemm<<<(N + 127) / 128, 256>>>(x, W1, as1, ad1, N);
    k_hist<<<(eThreads + 255) / 256, 256>>>(ei, E, vec);
    k_scanA<<<nScanBlocks, 1024>>>(N);
    k_scanB<<<1, 128>>>(N, nScanBlocks);
    k_scanC<<<nScanBlocks, 1024>>>(N);
    k_fill<<<(eThreads + 255) / 256, 256>>>(ei, E, vec);

    k2_gather<<<(N * 32 + 255) / 256, 256>>>(b1, N);
    k3_node<<<(N + 255) / 256, 256>>>(W2, as2, ad2, N);
    k45_gather_out<<<(N * 32 + 255) / 256, 256>>>(b2, out, N);
}

// round 4
// speedup vs baseline: 1.3199x; 1.0982x over previous
#include <cuda_runtime.h>
#include <math.h>

constexpr int FIN = 256;
constexpr int HC1 = 32;    // heads1 * out_ch1 = 2*16
constexpr int C2  = 40;
constexpr int NMAX = 100000;
constexpr int ETMAX = 3400000;   // E + N self loops
#define NEG 0.2f

// ---------------- scratch (device globals) ----------------
__device__ __align__(16) float g_h1[NMAX * HC1];
__device__ __align__(16) float g_asrc1[NMAX * 2];
__device__ __align__(16) float g_adst1[NMAX * 2];
__device__ __align__(16) float g_h1agg[NMAX * HC1];   // relu(agg + b1)
__device__ __align__(16) float g_h2[NMAX * C2];
__device__ float g_asrc2[NMAX];
__device__ float g_adst2[NMAX];
__device__ int g_deg[NMAX];
__device__ int g_rowstart[NMAX + 1];
__device__ int g_cursor[NMAX];
__device__ int g_partial[128];
__device__ int g_adj[ETMAX];

__device__ __forceinline__ void ffma2(unsigned long long& d, unsigned long long a, unsigned long long b) {
    asm("fma.rn.f32x2 %0, %1, %2, %0;" : "+l"(d) : "l"(a), "l"(b));
}

// ---------------------------------------------------------------------------
// K1: h1 = x @ W1 with f32x2 packed FMA; fused att-logit epilogue + deg init.
// ---------------------------------------------------------------------------
__global__ __launch_bounds__(256) void k1_gemm(
    const float* __restrict__ x, const float* __restrict__ W1,
    const float* __restrict__ as1v, const float* __restrict__ ad1v, int N) {
    __shared__ float2 xs2[128 * 33];
    __shared__ float wsc[32 * 32];
    int tid = threadIdx.x;
    int node0 = blockIdx.x * 128;

    if (tid < 128 && node0 + tid < N) g_deg[node0 + tid] = 1;  // self loop

    unsigned long long acc[4][2];
    #pragma unroll
    for (int j = 0; j < 4; j++) { acc[j][0] = 0ull; acc[j][1] = 0ull; }
    int r  = (tid >> 3) * 4;
    int cg = (tid & 7) * 4;

    for (int kc = 0; kc < 8; kc++) {
        __syncthreads();
        #pragma unroll
        for (int i = 0; i < 4; i++) wsc[tid + i * 256] = W1[kc * 32 * HC1 + tid + i * 256];
        #pragma unroll
        for (int i = 0; i < 16; i++) {
            int idx = tid + i * 256;
            int rr = idx >> 5, cc = idx & 31;
            int gr = node0 + rr;
            float v = (gr < N) ? x[(long long)gr * FIN + kc * 32 + cc] : 0.f;
            xs2[rr * 33 + cc] = make_float2(v, v);
        }
        __syncthreads();
        #pragma unroll
        for (int k = 0; k < 32; k++) {
            unsigned long long w01 = *(const unsigned long long*)&wsc[k * 32 + cg];
            unsigned long long w23 = *(const unsigned long long*)&wsc[k * 32 + cg + 2];
            #pragma unroll
            for (int j = 0; j < 4; j++) {
                unsigned long long xv = *(const unsigned long long*)&xs2[(r + j) * 33 + k];
                ffma2(acc[j][0], xv, w01);
                ffma2(acc[j][1], xv, w23);
            }
        }
    }

    float a0 = as1v[cg], a1 = as1v[cg + 1], a2 = as1v[cg + 2], a3 = as1v[cg + 3];
    float d0 = ad1v[cg], d1 = ad1v[cg + 1], d2 = ad1v[cg + 2], d3 = ad1v[cg + 3];
    int sub = tid & 7;
    #pragma unroll
    for (int j = 0; j < 4; j++) {
        float c0 = __uint_as_float((unsigned)acc[j][0]);
        float c1 = __uint_as_float((unsigned)(acc[j][0] >> 32));
        float c2 = __uint_as_float((unsigned)acc[j][1]);
        float c3 = __uint_as_float((unsigned)(acc[j][1] >> 32));
        int gr = node0 + r + j;
        float ps = c0 * a0 + c1 * a1 + c2 * a2 + c3 * a3;
        float pd = c0 * d0 + c1 * d1 + c2 * d2 + c3 * d3;
        ps += __shfl_xor_sync(0xffffffffu, ps, 1);
        pd += __shfl_xor_sync(0xffffffffu, pd, 1);
        ps += __shfl_xor_sync(0xffffffffu, ps, 2);
        pd += __shfl_xor_sync(0xffffffffu, pd, 2);
        if (gr < N) {
            *(float4*)&g_h1[gr * HC1 + cg] = make_float4(c0, c1, c2, c3);
            if (sub == 0)      { g_asrc1[2 * gr]     = ps; g_adst1[2 * gr]     = pd; }
            else if (sub == 4) { g_asrc1[2 * gr + 1] = ps; g_adst1[2 * gr + 1] = pd; }
        }
    }
}

// ---------------------------------------------------------------------------
// CSR build
// ---------------------------------------------------------------------------
__global__ void k_hist(const int* __restrict__ ei, int E, int vec) {
    int gid = blockIdx.x * blockDim.x + threadIdx.x;
    int e4 = gid * 4;
    if (e4 >= E) return;
    if (vec && e4 + 4 <= E) {
        int4 d = *(const int4*)&ei[E + e4];
        atomicAdd(&g_deg[d.x], 1);
        atomicAdd(&g_deg[d.y], 1);
        atomicAdd(&g_deg[d.z], 1);
        atomicAdd(&g_deg[d.w], 1);
    } else {
        for (int e = e4; e < E && e < e4 + 4; e++) atomicAdd(&g_deg[ei[E + e]], 1);
    }
}

__global__ void k_scanA(int N) {
    __shared__ int wsum[32];
    int tid = threadIdx.x, lane = tid & 31, warp = tid >> 5;
    int idx = blockIdx.x * 1024 + tid;
    int v = (idx < N) ? g_deg[idx] : 0;
    int sv = v;
    #pragma unroll
    for (int o = 1; o < 32; o <<= 1) {
        int t = __shfl_up_sync(0xffffffffu, sv, o);
        if (lane >= o) sv += t;
    }
    if (lane == 31) wsum[warp] = sv;
    __syncthreads();
    if (warp == 0) {
        int w = wsum[lane];
        int sw = w;
        #pragma unroll
        for (int o = 1; o < 32; o <<= 1) {
            int t = __shfl_up_sync(0xffffffffu, sw, o);
            if (lane >= o) sw += t;
        }
        wsum[lane] = sw - w;   // exclusive warp offset
    }
    __syncthreads();
    int incl = sv + wsum[warp];
    if (idx < N) g_rowstart[idx] = incl - v;
    if (tid == 1023) g_partial[blockIdx.x] = incl;
}

__global__ void k_scanB(int N, int nblocks) {
    __shared__ int wsum[4];
    int tid = threadIdx.x, lane = tid & 31, warp = tid >> 5;
    int v = (tid < nblocks) ? g_partial[tid] : 0;
    int sv = v;
    #pragma unroll
    for (int o = 1; o < 32; o <<= 1) {
        int t = __shfl_up_sync(0xffffffffu, sv, o);
        if (lane >= o) sv += t;
    }
    if (lane == 31) wsum[warp] = sv;
    __syncthreads();
    int base = 0;
    #pragma unroll
    for (int w = 0; w < 4; w++) base += (w < warp) ? wsum[w] : 0;
    int incl = sv + base;
    if (tid < nblocks) g_partial[tid] = incl - v;
    if (tid == 127) g_rowstart[N] = incl;
}

__global__ void k_scanC(int N) {
    int idx = blockIdx.x * 1024 + threadIdx.x;
    if (idx >= N) return;
    int rs = g_rowstart[idx] + g_partial[blockIdx.x];
    g_rowstart[idx] = rs;
    g_adj[rs] = idx;        // self loop first
    g_cursor[idx] = rs + 1;
}

__global__ void k_fill(const int* __restrict__ ei, int E, int vec) {
    int gid = blockIdx.x * blockDim.x + threadIdx.x;
    int e4 = gid * 4;
    if (e4 >= E) return;
    if (vec && e4 + 4 <= E) {
        int4 s = *(const int4*)&ei[e4];
        int4 d = *(const int4*)&ei[E + e4];
        g_adj[atomicAdd(&g_cursor[d.x], 1)] = s.x;
        g_adj[atomicAdd(&g_cursor[d.y], 1)] = s.y;
        g_adj[atomicAdd(&g_cursor[d.z], 1)] = s.z;
        g_adj[atomicAdd(&g_cursor[d.w], 1)] = s.w;
    } else {
        for (int e = e4; e < E && e < e4 + 4; e++)
            g_adj[atomicAdd(&g_cursor[ei[E + e]], 1)] = ei[e];
    }
}

// ---------------------------------------------------------------------------
// K2: layer-1 aggregation, chunked lane-parallel. One warp per dst node.
// Lane loads one neighbor's (src, exp-logits) per chunk; whole warp then
// sweeps the chunk from smem with 1 LDS.128 + 1 coalesced LDG per neighbor.
// ---------------------------------------------------------------------------
__global__ __launch_bounds__(256) void k2_gather(const float* __restrict__ b1, int N) {
    __shared__ uint4 sm[8][32];
    int warp = threadIdx.x >> 5, lane = threadIdx.x & 31;
    int n = blockIdx.x * 8 + warp;
    if (n >= N) return;
    float2 adst = *(const float2*)&g_adst1[2 * n];
    int start = g_rowstart[n], end = g_rowstart[n + 1];
    float acc = 0.f, evs0 = 0.f, evs1 = 0.f;
    for (int i = start; i < end; i += 32) {
        int idx = i + lane;
        bool valid = idx < end;
        int s = valid ? g_adj[idx] : 0;
        float2 l = valid ? *(const float2*)&g_asrc1[2 * s] : make_float2(0.f, 0.f);
        float a0 = l.x + adst.x; a0 = (a0 > 0.f) ? a0 : NEG * a0;
        float a1 = l.y + adst.y; a1 = (a1 > 0.f) ? a1 : NEG * a1;
        float e0 = valid ? __expf(a0) : 0.f;
        float e1 = valid ? __expf(a1) : 0.f;
        evs0 += e0; evs1 += e1;
        sm[warp][lane] = make_uint4((unsigned)s, __float_as_uint(e0), __float_as_uint(e1), 0u);
        __syncwarp();
        int cnt = min(32, end - i);
        #pragma unroll 4
        for (int j = 0; j < cnt; j++) {
            uint4 t = sm[warp][j];
            float v = g_h1[t.x * HC1 + lane];
            float eh = (lane < 16) ? __uint_as_float(t.y) : __uint_as_float(t.z);
            acc += eh * v;
        }
        __syncwarp();
    }
    #pragma unroll
    for (int o = 16; o >= 1; o >>= 1) {
        evs0 += __shfl_xor_sync(0xffffffffu, evs0, o);
        evs1 += __shfl_xor_sync(0xffffffffu, evs1, o);
    }
    float evs = (lane < 16) ? evs0 : evs1;
    g_h1agg[n * HC1 + lane] = fmaxf(acc / (evs + 1e-16f) + b1[lane], 0.f);
}

// ---------------------------------------------------------------------------
// K3: h2 = h1agg @ W2 [32x40] + layer-2 logits. Coalesced smem staging.
// ---------------------------------------------------------------------------
__global__ __launch_bounds__(256) void k3_node(
    const float* __restrict__ W2,
    const float* __restrict__ as2, const float* __restrict__ ad2, int N) {
    __shared__ float w2s[HC1 * C2];
    __shared__ float as2s[C2], ad2s[C2];
    __shared__ float hs[256 * 33];
    int tid = threadIdx.x;
    int node0 = blockIdx.x * 256;
    for (int i = tid; i < HC1 * C2; i += 256) w2s[i] = W2[i];
    if (tid < C2) { as2s[tid] = as2[tid]; ad2s[tid] = ad2[tid]; }

    int nmax = N - node0; if (nmax > 256) nmax = 256;
    for (int i = tid; i < 256 * 32; i += 256) {
        int nn = i >> 5, cc = i & 31;
        hs[nn * 33 + cc] = (nn < nmax) ? g_h1agg[(node0 + nn) * HC1 + cc] : 0.f;
    }
    __syncthreads();

    if (tid >= nmax) return;
    int n = node0 + tid;
    float acc[C2];
    #pragma unroll
    for (int c = 0; c < C2; c++) acc[c] = 0.f;
    #pragma unroll
    for (int k = 0; k < HC1; k++) {
        float rv = hs[tid * 33 + k];
        #pragma unroll
        for (int c = 0; c < C2; c++) acc[c] += rv * w2s[k * C2 + c];
    }
    float s2 = 0.f, d2 = 0.f;
    #pragma unroll
    for (int c = 0; c < C2; c += 4) {
        *(float4*)&g_h2[n * C2 + c] = make_float4(acc[c], acc[c+1], acc[c+2], acc[c+3]);
        s2 += acc[c]*as2s[c] + acc[c+1]*as2s[c+1] + acc[c+2]*as2s[c+2] + acc[c+3]*as2s[c+3];
        d2 += acc[c]*ad2s[c] + acc[c+1]*ad2s[c+1] + acc[c+2]*ad2s[c+2] + acc[c+3]*ad2s[c+3];
    }
    g_asrc2[n] = s2;
    g_adst2[n] = d2;
}

// ---------------------------------------------------------------------------
// K45: layer-2 aggregation, chunked lane-parallel, fused log_softmax.
// ---------------------------------------------------------------------------
__global__ __launch_bounds__(256) void k45_gather_out(
    const float* __restrict__ b2, float* __restrict__ out, int N) {
    __shared__ float2 sm[8][32];
    int warp = threadIdx.x >> 5, lane = threadIdx.x & 31;
    int n = blockIdx.x * 8 + warp;
    if (n >= N) return;
    float adstv = g_adst2[n];
    int start = g_rowstart[n], end = g_rowstart[n + 1];
    bool extra = lane < 8;
    float acc0 = 0.f, acc1 = 0.f, evs = 0.f;
    for (int i = start; i < end; i += 32) {
        int idx = i + lane;
        bool valid = idx < end;
        int s = valid ? g_adj[idx] : 0;
        float l = valid ? g_asrc2[s] : 0.f;
        float a = l + adstv; a = (a > 0.f) ? a : NEG * a;
        float e = valid ? __expf(a) : 0.f;
        evs += e;
        sm[warp][lane] = make_float2(__int_as_float(s), e);
        __syncwarp();
        int cnt = min(32, end - i);
        #pragma unroll 4
        for (int j = 0; j < cnt; j++) {
            float2 t = sm[warp][j];
            int sj = __float_as_int(t.x);
            acc0 += t.y * g_h2[sj * C2 + lane];
            if (extra) acc1 += t.y * g_h2[sj * C2 + 32 + lane];
        }
        __syncwarp();
    }
    #pragma unroll
    for (int o = 16; o >= 1; o >>= 1) evs += __shfl_xor_sync(0xffffffffu, evs, o);
    float inv = 1.f / (evs + 1e-16f);
    float v0 = acc0 * inv + b2[lane];
    float v1 = extra ? (acc1 * inv + b2[32 + lane]) : -INFINITY;
    float m = fmaxf(v0, v1);
    #pragma unroll
    for (int o = 16; o >= 1; o >>= 1) m = fmaxf(m, __shfl_xor_sync(0xffffffffu, m, o));
    float ssum = expf(v0 - m) + (extra ? expf(v1 - m) : 0.f);
    #pragma unroll
    for (int o = 16; o >= 1; o >>= 1) ssum += __shfl_xor_sync(0xffffffffu, ssum, o);
    float lse = logf(ssum);
    out[n * C2 + lane] = v0 - m - lse;
    if (extra) out[n * C2 + 32 + lane] = v1 - m - lse;
}

// ---------------------------------------------------------------------------
extern "C" void kernel_launch(void* const* d_in, const int* in_sizes, int n_in,
                              void* d_out, int out_size) {
    const float* x   = (const float*)d_in[0];
    const int*   ei  = (const int*)d_in[1];
    const float* W1  = (const float*)d_in[2];
    const float* as1 = (const float*)d_in[3];
    const float* ad1 = (const float*)d_in[4];
    const float* b1  = (const float*)d_in[5];
    const float* W2  = (const float*)d_in[6];
    const float* as2 = (const float*)d_in[7];
    const float* ad2 = (const float*)d_in[8];
    const float* b2  = (const float*)d_in[9];
    float* out = (float*)d_out;

    int N  = in_sizes[0] / FIN;
    int E  = in_sizes[1] / 2;
    int vec = ((E & 3) == 0) ? 1 : 0;
    int nScanBlocks = (N + 1023) / 1024;
    int eThreads = (E + 3) / 4;

    k1_gemm<<<(N + 127) / 128, 256>>>(x, W1, as1, ad1, N);
    k_hist<<<(eThreads + 255) / 256, 256>>>(ei, E, vec);
    k_scanA<<<nScanBlocks, 1024>>>(N);
    k_scanB<<<1, 128>>>(N, nScanBlocks);
    k_scanC<<<nScanBlocks, 1024>>>(N);
    k_fill<<<(eThreads + 255) / 256, 256>>>(ei, E, vec);

    k2_gather<<<(N + 7) / 8, 256>>>(b1, N);
    k3_node<<<(N + 255) / 256, 256>>>(W2, as2, ad2, N);
    k45_gather_out<<<(N + 7) / 8, 256>>>(b2, out, N);
}

// round 5
// speedup vs baseline: 1.3470x; 1.0205x over previous
#include <cuda_runtime.h>
#include <cuda_fp16.h>
#include <math.h>

constexpr int FIN = 256;
constexpr int HC1 = 32;    // heads1 * out_ch1 = 2*16
constexpr int C2  = 40;
constexpr int H2STRIDE = 64;  // halves; 128B padded stride for h2 rows
constexpr int NMAX = 100000;
constexpr int ETMAX = 3400000;   // E + N self loops
#define NEG 0.2f

// ---------------- scratch (device globals) ----------------
__device__ __align__(16) __half g_h1h[NMAX * HC1];        // fp16 h1 (gather payload)
__device__ __align__(16) float g_asrc1[NMAX * 2];
__device__ __align__(16) float g_adst1[NMAX * 2];
__device__ __align__(16) float g_h1agg[NMAX * HC1];       // relu(agg + b1)
__device__ __align__(16) __half g_h2h[NMAX * H2STRIDE];   // fp16 h2, 128B stride
__device__ float g_asrc2[NMAX];
__device__ float g_adst2[NMAX];
__device__ int g_deg[NMAX];
__device__ int g_rowstart[NMAX + 1];
__device__ int g_cursor[NMAX];
__device__ int g_partial[128];
__device__ int g_adj[ETMAX];

__device__ __forceinline__ void ffma2(unsigned long long& d, unsigned long long a, unsigned long long b) {
    asm("fma.rn.f32x2 %0, %1, %2, %0;" : "+l"(d) : "l"(a), "l"(b));
}

// ---------------------------------------------------------------------------
// K1: h1 = x @ W1 (f32x2 packed FMA); epilogue: fp16 h1 + att logits + deg=1.
// ---------------------------------------------------------------------------
__global__ __launch_bounds__(256) void k1_gemm(
    const float* __restrict__ x, const float* __restrict__ W1,
    const float* __restrict__ as1v, const float* __restrict__ ad1v, int N) {
    __shared__ float2 xs2[128 * 33];
    __shared__ float wsc[32 * 32];
    int tid = threadIdx.x;
    int node0 = blockIdx.x * 128;

    if (tid < 128 && node0 + tid < N) g_deg[node0 + tid] = 1;  // self loop

    unsigned long long acc[4][2];
    #pragma unroll
    for (int j = 0; j < 4; j++) { acc[j][0] = 0ull; acc[j][1] = 0ull; }
    int r  = (tid >> 3) * 4;
    int cg = (tid & 7) * 4;

    for (int kc = 0; kc < 8; kc++) {
        __syncthreads();
        #pragma unroll
        for (int i = 0; i < 4; i++) wsc[tid + i * 256] = W1[kc * 32 * HC1 + tid + i * 256];
        #pragma unroll
        for (int i = 0; i < 16; i++) {
            int idx = tid + i * 256;
            int rr = idx >> 5, cc = idx & 31;
            int gr = node0 + rr;
            float v = (gr < N) ? x[(long long)gr * FIN + kc * 32 + cc] : 0.f;
            xs2[rr * 33 + cc] = make_float2(v, v);
        }
        __syncthreads();
        #pragma unroll
        for (int k = 0; k < 32; k++) {
            unsigned long long w01 = *(const unsigned long long*)&wsc[k * 32 + cg];
            unsigned long long w23 = *(const unsigned long long*)&wsc[k * 32 + cg + 2];
            #pragma unroll
            for (int j = 0; j < 4; j++) {
                unsigned long long xv = *(const unsigned long long*)&xs2[(r + j) * 33 + k];
                ffma2(acc[j][0], xv, w01);
                ffma2(acc[j][1], xv, w23);
            }
        }
    }

    float a0 = as1v[cg], a1 = as1v[cg + 1], a2 = as1v[cg + 2], a3 = as1v[cg + 3];
    float d0 = ad1v[cg], d1 = ad1v[cg + 1], d2 = ad1v[cg + 2], d3 = ad1v[cg + 3];
    int sub = tid & 7;
    #pragma unroll
    for (int j = 0; j < 4; j++) {
        float c0 = __uint_as_float((unsigned)acc[j][0]);
        float c1 = __uint_as_float((unsigned)(acc[j][0] >> 32));
        float c2 = __uint_as_float((unsigned)acc[j][1]);
        float c3 = __uint_as_float((unsigned)(acc[j][1] >> 32));
        int gr = node0 + r + j;
        float ps = c0 * a0 + c1 * a1 + c2 * a2 + c3 * a3;
        float pd = c0 * d0 + c1 * d1 + c2 * d2 + c3 * d3;
        ps += __shfl_xor_sync(0xffffffffu, ps, 1);
        pd += __shfl_xor_sync(0xffffffffu, pd, 1);
        ps += __shfl_xor_sync(0xffffffffu, ps, 2);
        pd += __shfl_xor_sync(0xffffffffu, pd, 2);
        if (gr < N) {
            __half2 p01 = __floats2half2_rn(c0, c1);
            __half2 p23 = __floats2half2_rn(c2, c3);
            uint2 pk = make_uint2(*(unsigned*)&p01, *(unsigned*)&p23);
            *(uint2*)&g_h1h[gr * HC1 + cg] = pk;
            if (sub == 0)      { g_asrc1[2 * gr]     = ps; g_adst1[2 * gr]     = pd; }
            else if (sub == 4) { g_asrc1[2 * gr + 1] = ps; g_adst1[2 * gr + 1] = pd; }
        }
    }
}

// ---------------------------------------------------------------------------
// CSR build
// ---------------------------------------------------------------------------
__global__ void k_hist(const int* __restrict__ ei, int E, int vec) {
    int gid = blockIdx.x * blockDim.x + threadIdx.x;
    int e4 = gid * 4;
    if (e4 >= E) return;
    if (vec && e4 + 4 <= E) {
        int4 d = *(const int4*)&ei[E + e4];
        atomicAdd(&g_deg[d.x], 1);
        atomicAdd(&g_deg[d.y], 1);
        atomicAdd(&g_deg[d.z], 1);
        atomicAdd(&g_deg[d.w], 1);
    } else {
        for (int e = e4; e < E && e < e4 + 4; e++) atomicAdd(&g_deg[ei[E + e]], 1);
    }
}

__global__ void k_scanA(int N) {
    __shared__ int wsum[32];
    int tid = threadIdx.x, lane = tid & 31, warp = tid >> 5;
    int idx = blockIdx.x * 1024 + tid;
    int v = (idx < N) ? g_deg[idx] : 0;
    int sv = v;
    #pragma unroll
    for (int o = 1; o < 32; o <<= 1) {
        int t = __shfl_up_sync(0xffffffffu, sv, o);
        if (lane >= o) sv += t;
    }
    if (lane == 31) wsum[warp] = sv;
    __syncthreads();
    if (warp == 0) {
        int w = wsum[lane];
        int sw = w;
        #pragma unroll
        for (int o = 1; o < 32; o <<= 1) {
            int t = __shfl_up_sync(0xffffffffu, sw, o);
            if (lane >= o) sw += t;
        }
        wsum[lane] = sw - w;
    }
    __syncthreads();
    int incl = sv + wsum[warp];
    if (idx < N) g_rowstart[idx] = incl - v;
    if (tid == 1023) g_partial[blockIdx.x] = incl;
}

__global__ void k_scanB(int N, int nblocks) {
    __shared__ int wsum[4];
    int tid = threadIdx.x, lane = tid & 31, warp = tid >> 5;
    int v = (tid < nblocks) ? g_partial[tid] : 0;
    int sv = v;
    #pragma unroll
    for (int o = 1; o < 32; o <<= 1) {
        int t = __shfl_up_sync(0xffffffffu, sv, o);
        if (lane >= o) sv += t;
    }
    if (lane == 31) wsum[warp] = sv;
    __syncthreads();
    int base = 0;
    #pragma unroll
    for (int w = 0; w < 4; w++) base += (w < warp) ? wsum[w] : 0;
    int incl = sv + base;
    if (tid < nblocks) g_partial[tid] = incl - v;
    if (tid == 127) g_rowstart[N] = incl;
}

__global__ void k_scanC(int N) {
    int idx = blockIdx.x * 1024 + threadIdx.x;
    if (idx >= N) return;
    int rs = g_rowstart[idx] + g_partial[blockIdx.x];
    g_rowstart[idx] = rs;
    g_adj[rs] = idx;
    g_cursor[idx] = rs + 1;
}

__global__ void k_fill(const int* __restrict__ ei, int E, int vec) {
    int gid = blockIdx.x * blockDim.x + threadIdx.x;
    int e4 = gid * 4;
    if (e4 >= E) return;
    if (vec && e4 + 4 <= E) {
        int4 s = *(const int4*)&ei[e4];
        int4 d = *(const int4*)&ei[E + e4];
        g_adj[atomicAdd(&g_cursor[d.x], 1)] = s.x;
        g_adj[atomicAdd(&g_cursor[d.y], 1)] = s.y;
        g_adj[atomicAdd(&g_cursor[d.z], 1)] = s.z;
        g_adj[atomicAdd(&g_cursor[d.w], 1)] = s.w;
    } else {
        for (int e = e4; e < E && e < e4 + 4; e++)
            g_adj[atomicAdd(&g_cursor[ei[E + e]], 1)] = ei[e];
    }
}

// ---------------------------------------------------------------------------
// K2: layer-1 aggregation, chunked lane-parallel, fp16 values.
// ---------------------------------------------------------------------------
__global__ __launch_bounds__(256) void k2_gather(const float* __restrict__ b1, int N) {
    __shared__ uint4 sm[8][32];
    int warp = threadIdx.x >> 5, lane = threadIdx.x & 31;
    int n = blockIdx.x * 8 + warp;
    if (n >= N) return;
    float2 adst = *(const float2*)&g_adst1[2 * n];
    int start = g_rowstart[n], end = g_rowstart[n + 1];
    float acc = 0.f, evs0 = 0.f, evs1 = 0.f;
    for (int i = start; i < end; i += 32) {
        int idx = i + lane;
        bool valid = idx < end;
        int s = valid ? g_adj[idx] : 0;
        float2 l = valid ? *(const float2*)&g_asrc1[2 * s] : make_float2(0.f, 0.f);
        float a0 = l.x + adst.x; a0 = (a0 > 0.f) ? a0 : NEG * a0;
        float a1 = l.y + adst.y; a1 = (a1 > 0.f) ? a1 : NEG * a1;
        float e0 = valid ? __expf(a0) : 0.f;
        float e1 = valid ? __expf(a1) : 0.f;
        evs0 += e0; evs1 += e1;
        sm[warp][lane] = make_uint4((unsigned)s, __float_as_uint(e0), __float_as_uint(e1), 0u);
        __syncwarp();
        int cnt = min(32, end - i);
        #pragma unroll 8
        for (int j = 0; j < cnt; j++) {
            uint4 t = sm[warp][j];
            float v = __half2float(g_h1h[t.x * HC1 + lane]);
            float eh = (lane < 16) ? __uint_as_float(t.y) : __uint_as_float(t.z);
            acc += eh * v;
        }
        __syncwarp();
    }
    #pragma unroll
    for (int o = 16; o >= 1; o >>= 1) {
        evs0 += __shfl_xor_sync(0xffffffffu, evs0, o);
        evs1 += __shfl_xor_sync(0xffffffffu, evs1, o);
    }
    float evs = (lane < 16) ? evs0 : evs1;
    g_h1agg[n * HC1 + lane] = fmaxf(acc / (evs + 1e-16f) + b1[lane], 0.f);
}

// ---------------------------------------------------------------------------
// K3: h2 = h1agg @ W2 [32x40] (fp16 out, 128B stride) + layer-2 logits.
// ---------------------------------------------------------------------------
__global__ __launch_bounds__(256) void k3_node(
    const float* __restrict__ W2,
    const float* __restrict__ as2, const float* __restrict__ ad2, int N) {
    __shared__ float w2s[HC1 * C2];
    __shared__ float as2s[C2], ad2s[C2];
    __shared__ float hs[256 * 33];
    int tid = threadIdx.x;
    int node0 = blockIdx.x * 256;
    for (int i = tid; i < HC1 * C2; i += 256) w2s[i] = W2[i];
    if (tid < C2) { as2s[tid] = as2[tid]; ad2s[tid] = ad2[tid]; }

    int nmax = N - node0; if (nmax > 256) nmax = 256;
    for (int i = tid; i < 256 * 32; i += 256) {
        int nn = i >> 5, cc = i & 31;
        hs[nn * 33 + cc] = (nn < nmax) ? g_h1agg[(node0 + nn) * HC1 + cc] : 0.f;
    }
    __syncthreads();

    if (tid >= nmax) return;
    int n = node0 + tid;
    float acc[C2];
    #pragma unroll
    for (int c = 0; c < C2; c++) acc[c] = 0.f;
    #pragma unroll
    for (int k = 0; k < HC1; k++) {
        float rv = hs[tid * 33 + k];
        #pragma unroll
        for (int c = 0; c < C2; c++) acc[c] += rv * w2s[k * C2 + c];
    }
    float s2 = 0.f, d2 = 0.f;
    #pragma unroll
    for (int c = 0; c < C2; c += 8) {
        __half2 p0 = __floats2half2_rn(acc[c],     acc[c + 1]);
        __half2 p1 = __floats2half2_rn(acc[c + 2], acc[c + 3]);
        __half2 p2 = __floats2half2_rn(acc[c + 4], acc[c + 5]);
        __half2 p3 = __floats2half2_rn(acc[c + 6], acc[c + 7]);
        uint4 pk = make_uint4(*(unsigned*)&p0, *(unsigned*)&p1, *(unsigned*)&p2, *(unsigned*)&p3);
        *(uint4*)&g_h2h[n * H2STRIDE + c] = pk;
    }
    #pragma unroll
    for (int c = 0; c < C2; c++) {
        s2 += acc[c] * as2s[c];
        d2 += acc[c] * ad2s[c];
    }
    g_asrc2[n] = s2;
    g_adst2[n] = d2;
}

// ---------------------------------------------------------------------------
// K45: layer-2 aggregation (fp16 values, 2 ch/lane) + fused log_softmax.
// ---------------------------------------------------------------------------
__global__ __launch_bounds__(256) void k45_gather_out(
    const float* __restrict__ b2, float* __restrict__ out, int N) {
    __shared__ float2 sm[8][32];
    int warp = threadIdx.x >> 5, lane = threadIdx.x & 31;
    int n = blockIdx.x * 8 + warp;
    if (n >= N) return;
    float adstv = g_adst2[n];
    int start = g_rowstart[n], end = g_rowstart[n + 1];
    bool act = lane < 20;   // lanes 0..19 hold channels 2*lane, 2*lane+1
    float accx = 0.f, accy = 0.f, evs = 0.f;
    for (int i = start; i < end; i += 32) {
        int idx = i + lane;
        bool valid = idx < end;
        int s = valid ? g_adj[idx] : 0;
        float l = valid ? g_asrc2[s] : 0.f;
        float a = l + adstv; a = (a > 0.f) ? a : NEG * a;
        float e = valid ? __expf(a) : 0.f;
        evs += e;
        sm[warp][lane] = make_float2(__int_as_float(s), e);
        __syncwarp();
        int cnt = min(32, end - i);
        if (act) {
            #pragma unroll 8
            for (int j = 0; j < cnt; j++) {
                float2 t = sm[warp][j];
                int sj = __float_as_int(t.x);
                __half2 hv = *(const __half2*)&g_h2h[sj * H2STRIDE + 2 * lane];
                float2 fv = __half22float2(hv);
                accx += t.y * fv.x;
                accy += t.y * fv.y;
            }
        }
        __syncwarp();
    }
    #pragma unroll
    for (int o = 16; o >= 1; o >>= 1) evs += __shfl_xor_sync(0xffffffffu, evs, o);
    float inv = 1.f / (evs + 1e-16f);
    float v0 = act ? (accx * inv + b2[2 * lane])     : -INFINITY;
    float v1 = act ? (accy * inv + b2[2 * lane + 1]) : -INFINITY;
    float m = fmaxf(v0, v1);
    #pragma unroll
    for (int o = 16; o >= 1; o >>= 1) m = fmaxf(m, __shfl_xor_sync(0xffffffffu, m, o));
    float ssum = act ? (expf(v0 - m) + expf(v1 - m)) : 0.f;
    #pragma unroll
    for (int o = 16; o >= 1; o >>= 1) ssum += __shfl_xor_sync(0xffffffffu, ssum, o);
    float lse = logf(ssum);
    if (act) {
        out[n * C2 + 2 * lane]     = v0 - m - lse;
        out[n * C2 + 2 * lane + 1] = v1 - m - lse;
    }
}

// ---------------------------------------------------------------------------
extern "C" void kernel_launch(void* const* d_in, const int* in_sizes, int n_in,
                              void* d_out, int out_size) {
    const float* x   = (const float*)d_in[0];
    const int*   ei  = (const int*)d_in[1];
    const float* W1  = (const float*)d_in[2];
    const float* as1 = (const float*)d_in[3];
    const float* ad1 = (const float*)d_in[4];
    const float* b1  = (const float*)d_in[5];
    const float* W2  = (const float*)d_in[6];
    const float* as2 = (const float*)d_in[7];
    const float* ad2 = (const float*)d_in[8];
    const float* b2  = (const float*)d_in[9];
    float* out = (float*)d_out;

    int N  = in_sizes[0] / FIN;
    int E  = in_sizes[1] / 2;
    int vec = ((E & 3) == 0) ? 1 : 0;
    int nScanBlocks = (N + 1023) / 1024;
    int eThreads = (E + 3) / 4;

    k1_gemm<<<(N + 127) / 128, 256>>>(x, W1, as1, ad1, N);
    k_hist<<<(eThreads + 255) / 256, 256>>>(ei, E, vec);
    k_scanA<<<nScanBlocks, 1024>>>(N);
    k_scanB<<<1, 128>>>(N, nScanBlocks);
    k_scanC<<<nScanBlocks, 1024>>>(N);
    k_fill<<<(eThreads + 255) / 256, 256>>>(ei, E, vec);

    k2_gather<<<(N + 7) / 8, 256>>>(b1, N);
    k3_node<<<(N + 255) / 256, 256>>>(W2, as2, ad2, N);
    k45_gather_out<<<(N + 7) / 8, 256>>>(b2, out, N);
}

// round 6
// speedup vs baseline: 1.3509x; 1.0029x over previous
#include <cuda_runtime.h>
#include <cuda_fp16.h>
#include <math.h>

constexpr int FIN = 256;
constexpr int HC1 = 32;    // heads1 * out_ch1 = 2*16
constexpr int C2  = 40;
constexpr int H2STRIDE = 64;  // halves; 128B padded stride for h2 rows
constexpr int NMAX = 100000;
constexpr int ETMAX = 3400000;   // E + N self loops
#define NEG 0.2f

// ---------------- scratch (device globals) ----------------
__device__ __align__(16) __half g_h1h[NMAX * HC1];        // fp16 h1 (gather payload)
__device__ __align__(16) float g_asrc1[NMAX * 2];
__device__ __align__(16) float g_adst1[NMAX * 2];
__device__ __align__(16) float g_h1agg[NMAX * HC1];       // relu(agg + b1)
__device__ __align__(16) __half g_h2h[NMAX * H2STRIDE];   // fp16 h2, 128B stride
__device__ float g_asrc2[NMAX];
__device__ float g_adst2[NMAX];
__device__ int g_deg[NMAX];          // zero-initialized; re-zeroed by k_scan1 each replay
__device__ int g_rowstart[NMAX + 1];
__device__ int g_cursor[NMAX];
__device__ int g_adj[ETMAX];
// decoupled-lookback scan state (reset by k_hist each replay)
__device__ int g_scan_flag[128];
__device__ int g_scan_agg[128];
__device__ int g_scan_pref[128];

__device__ __forceinline__ void ffma2(unsigned long long& d, unsigned long long a, unsigned long long b) {
    asm("fma.rn.f32x2 %0, %1, %2, %0;" : "+l"(d) : "l"(a), "l"(b));
}

// ---------------------------------------------------------------------------
// K1: h1 = x @ W1 (f32x2 packed FMA); epilogue: fp16 h1 + att logits.
// ---------------------------------------------------------------------------
__global__ __launch_bounds__(256) void k1_gemm(
    const float* __restrict__ x, const float* __restrict__ W1,
    const float* __restrict__ as1v, const float* __restrict__ ad1v, int N) {
    __shared__ float2 xs2[128 * 33];
    __shared__ float wsc[32 * 32];
    int tid = threadIdx.x;
    int node0 = blockIdx.x * 128;

    unsigned long long acc[4][2];
    #pragma unroll
    for (int j = 0; j < 4; j++) { acc[j][0] = 0ull; acc[j][1] = 0ull; }
    int r  = (tid >> 3) * 4;
    int cg = (tid & 7) * 4;

    for (int kc = 0; kc < 8; kc++) {
        __syncthreads();
        #pragma unroll
        for (int i = 0; i < 4; i++) wsc[tid + i * 256] = W1[kc * 32 * HC1 + tid + i * 256];
        #pragma unroll
        for (int i = 0; i < 16; i++) {
            int idx = tid + i * 256;
            int rr = idx >> 5, cc = idx & 31;
            int gr = node0 + rr;
            float v = (gr < N) ? x[(long long)gr * FIN + kc * 32 + cc] : 0.f;
            xs2[rr * 33 + cc] = make_float2(v, v);
        }
        __syncthreads();
        #pragma unroll
        for (int k = 0; k < 32; k++) {
            unsigned long long w01 = *(const unsigned long long*)&wsc[k * 32 + cg];
            unsigned long long w23 = *(const unsigned long long*)&wsc[k * 32 + cg + 2];
            #pragma unroll
            for (int j = 0; j < 4; j++) {
                unsigned long long xv = *(const unsigned long long*)&xs2[(r + j) * 33 + k];
                ffma2(acc[j][0], xv, w01);
                ffma2(acc[j][1], xv, w23);
            }
        }
    }

    float a0 = as1v[cg], a1 = as1v[cg + 1], a2 = as1v[cg + 2], a3 = as1v[cg + 3];
    float d0 = ad1v[cg], d1 = ad1v[cg + 1], d2 = ad1v[cg + 2], d3 = ad1v[cg + 3];
    int sub = tid & 7;
    #pragma unroll
    for (int j = 0; j < 4; j++) {
        float c0 = __uint_as_float((unsigned)acc[j][0]);
        float c1 = __uint_as_float((unsigned)(acc[j][0] >> 32));
        float c2 = __uint_as_float((unsigned)acc[j][1]);
        float c3 = __uint_as_float((unsigned)(acc[j][1] >> 32));
        int gr = node0 + r + j;
        float ps = c0 * a0 + c1 * a1 + c2 * a2 + c3 * a3;
        float pd = c0 * d0 + c1 * d1 + c2 * d2 + c3 * d3;
        ps += __shfl_xor_sync(0xffffffffu, ps, 1);
        pd += __shfl_xor_sync(0xffffffffu, pd, 1);
        ps += __shfl_xor_sync(0xffffffffu, ps, 2);
        pd += __shfl_xor_sync(0xffffffffu, pd, 2);
        if (gr < N) {
            __half2 p01 = __floats2half2_rn(c0, c1);
            __half2 p23 = __floats2half2_rn(c2, c3);
            uint2 pk = make_uint2(*(unsigned*)&p01, *(unsigned*)&p23);
            *(uint2*)&g_h1h[gr * HC1 + cg] = pk;
            if (sub == 0)      { g_asrc1[2 * gr]     = ps; g_adst1[2 * gr]     = pd; }
            else if (sub == 4) { g_asrc1[2 * gr + 1] = ps; g_adst1[2 * gr + 1] = pd; }
        }
    }
}

// ---------------------------------------------------------------------------
// CSR build: hist (+scan-flag reset) -> single-pass lookback scan -> fill
// ---------------------------------------------------------------------------
__global__ void k_hist(const int* __restrict__ ei, int E, int vec) {
    int gid = blockIdx.x * blockDim.x + threadIdx.x;
    if (gid < 128) g_scan_flag[gid] = 0;   // reset lookback state for this replay
    int e4 = gid * 4;
    if (e4 >= E) return;
    if (vec && e4 + 4 <= E) {
        int4 d = *(const int4*)&ei[E + e4];
        atomicAdd(&g_deg[d.x], 1);
        atomicAdd(&g_deg[d.y], 1);
        atomicAdd(&g_deg[d.z], 1);
        atomicAdd(&g_deg[d.w], 1);
    } else {
        for (int e = e4; e < E && e < e4 + 4; e++) atomicAdd(&g_deg[ei[E + e]], 1);
    }
}

// Single-pass scan with decoupled lookback. deg+1 (self loop) -> rowstart,
// cursor, adj self-loop slot. Re-zeros g_deg for the next replay.
__global__ __launch_bounds__(1024) void k_scan1(int N) {
    __shared__ int wsum[32];
    __shared__ int s_total;
    __shared__ int s_exc;
    int tid = threadIdx.x, lane = tid & 31, warp = tid >> 5;
    int bid = blockIdx.x;
    int idx = bid * 1024 + tid;

    int v = 0;
    if (idx < N) { v = g_deg[idx] + 1; g_deg[idx] = 0; }

    int sv = v;
    #pragma unroll
    for (int o = 1; o < 32; o <<= 1) {
        int t = __shfl_up_sync(0xffffffffu, sv, o);
        if (lane >= o) sv += t;
    }
    if (lane == 31) wsum[warp] = sv;
    __syncthreads();
    if (warp == 0) {
        int w = wsum[lane];
        int sw = w;
        #pragma unroll
        for (int o = 1; o < 32; o <<= 1) {
            int t = __shfl_up_sync(0xffffffffu, sw, o);
            if (lane >= o) sw += t;
        }
        wsum[lane] = sw - w;        // exclusive warp offsets
        if (lane == 31) s_total = sw;
    }
    __syncthreads();
    int incl = sv + wsum[warp];
    int total = s_total;

    if (tid == 0) {
        if (bid == 0) {
            g_scan_pref[0] = total;
            __threadfence();
            g_scan_flag[0] = 2;
            s_exc = 0;
        } else {
            g_scan_agg[bid] = total;
            __threadfence();
            g_scan_flag[bid] = 1;
            // lookback
            int exc = 0;
            for (int j = bid - 1;;) {
                int f;
                do { f = *(volatile int*)&g_scan_flag[j]; } while (f == 0);
                __threadfence();
                if (f == 2) { exc += *(volatile int*)&g_scan_pref[j]; break; }
                exc += *(volatile int*)&g_scan_agg[j];
                j--;
            }
            g_scan_pref[bid] = exc + total;
            __threadfence();
            g_scan_flag[bid] = 2;
            s_exc = exc;
        }
    }
    __syncthreads();
    int base = s_exc;
    if (idx < N) {
        int rs = base + incl - v;
        g_rowstart[idx] = rs;
        g_adj[rs] = idx;            // self loop first
        g_cursor[idx] = rs + 1;
        if (idx == N - 1) g_rowstart[N] = base + incl;
    }
}

__global__ void k_fill(const int* __restrict__ ei, int E, int vec) {
    int gid = blockIdx.x * blockDim.x + threadIdx.x;
    int e4 = gid * 4;
    if (e4 >= E) return;
    if (vec && e4 + 4 <= E) {
        int4 s = *(const int4*)&ei[e4];
        int4 d = *(const int4*)&ei[E + e4];
        g_adj[atomicAdd(&g_cursor[d.x], 1)] = s.x;
        g_adj[atomicAdd(&g_cursor[d.y], 1)] = s.y;
        g_adj[atomicAdd(&g_cursor[d.z], 1)] = s.z;
        g_adj[atomicAdd(&g_cursor[d.w], 1)] = s.w;
    } else {
        for (int e = e4; e < E && e < e4 + 4; e++)
            g_adj[atomicAdd(&g_cursor[ei[E + e]], 1)] = ei[e];
    }
}

// ---------------------------------------------------------------------------
// K2: layer-1 aggregation, chunked lane-parallel, fp16 values.
// ---------------------------------------------------------------------------
__global__ __launch_bounds__(256) void k2_gather(const float* __restrict__ b1, int N) {
    __shared__ uint4 sm[8][32];
    int warp = threadIdx.x >> 5, lane = threadIdx.x & 31;
    int n = blockIdx.x * 8 + warp;
    if (n >= N) return;
    float2 adst = *(const float2*)&g_adst1[2 * n];
    int start = g_rowstart[n], end = g_rowstart[n + 1];
    float acc = 0.f, evs0 = 0.f, evs1 = 0.f;
    for (int i = start; i < end; i += 32) {
        int idx = i + lane;
        bool valid = idx < end;
        int s = valid ? g_adj[idx] : 0;
        float2 l = valid ? *(const float2*)&g_asrc1[2 * s] : make_float2(0.f, 0.f);
        float a0 = l.x + adst.x; a0 = (a0 > 0.f) ? a0 : NEG * a0;
        float a1 = l.y + adst.y; a1 = (a1 > 0.f) ? a1 : NEG * a1;
        float e0 = valid ? __expf(a0) : 0.f;
        float e1 = valid ? __expf(a1) : 0.f;
        evs0 += e0; evs1 += e1;
        sm[warp][lane] = make_uint4((unsigned)s, __float_as_uint(e0), __float_as_uint(e1), 0u);
        __syncwarp();
        int cnt = min(32, end - i);
        #pragma unroll 8
        for (int j = 0; j < cnt; j++) {
            uint4 t = sm[warp][j];
            float v = __half2float(g_h1h[t.x * HC1 + lane]);
            float eh = (lane < 16) ? __uint_as_float(t.y) : __uint_as_float(t.z);
            acc += eh * v;
        }
        __syncwarp();
    }
    #pragma unroll
    for (int o = 16; o >= 1; o >>= 1) {
        evs0 += __shfl_xor_sync(0xffffffffu, evs0, o);
        evs1 += __shfl_xor_sync(0xffffffffu, evs1, o);
    }
    float evs = (lane < 16) ? evs0 : evs1;
    g_h1agg[n * HC1 + lane] = fmaxf(acc / (evs + 1e-16f) + b1[lane], 0.f);
}

// ---------------------------------------------------------------------------
// K3: h2 = h1agg @ W2 [32x40] (fp16 out, 128B stride) + layer-2 logits.
// ---------------------------------------------------------------------------
__global__ __launch_bounds__(256) void k3_node(
    const float* __restrict__ W2,
    const float* __restrict__ as2, const float* __restrict__ ad2, int N) {
    __shared__ float w2s[HC1 * C2];
    __shared__ float as2s[C2], ad2s[C2];
    __shared__ float hs[256 * 33];
    int tid = threadIdx.x;
    int node0 = blockIdx.x * 256;
    for (int i = tid; i < HC1 * C2; i += 256) w2s[i] = W2[i];
    if (tid < C2) { as2s[tid] = as2[tid]; ad2s[tid] = ad2[tid]; }

    int nmax = N - node0; if (nmax > 256) nmax = 256;
    for (int i = tid; i < 256 * 32; i += 256) {
        int nn = i >> 5, cc = i & 31;
        hs[nn * 33 + cc] = (nn < nmax) ? g_h1agg[(node0 + nn) * HC1 + cc] : 0.f;
    }
    __syncthreads();

    if (tid >= nmax) return;
    int n = node0 + tid;
    float acc[C2];
    #pragma unroll
    for (int c = 0; c < C2; c++) acc[c] = 0.f;
    #pragma unroll
    for (int k = 0; k < HC1; k++) {
        float rv = hs[tid * 33 + k];
        #pragma unroll
        for (int c = 0; c < C2; c++) acc[c] += rv * w2s[k * C2 + c];
    }
    float s2 = 0.f, d2 = 0.f;
    #pragma unroll
    for (int c = 0; c < C2; c += 8) {
        __half2 p0 = __floats2half2_rn(acc[c],     acc[c + 1]);
        __half2 p1 = __floats2half2_rn(acc[c + 2], acc[c + 3]);
        __half2 p2 = __floats2half2_rn(acc[c + 4], acc[c + 5]);
        __half2 p3 = __floats2half2_rn(acc[c + 6], acc[c + 7]);
        uint4 pk = make_uint4(*(unsigned*)&p0, *(unsigned*)&p1, *(unsigned*)&p2, *(unsigned*)&p3);
        *(uint4*)&g_h2h[n * H2STRIDE + c] = pk;
    }
    #pragma unroll
    for (int c = 0; c < C2; c++) {
        s2 += acc[c] * as2s[c];
        d2 += acc[c] * ad2s[c];
    }
    g_asrc2[n] = s2;
    g_adst2[n] = d2;
}

// ---------------------------------------------------------------------------
// K45: layer-2 aggregation (fp16 values, 2 ch/lane) + fused log_softmax.
// ---------------------------------------------------------------------------
__global__ __launch_bounds__(256) void k45_gather_out(
    const float* __restrict__ b2, float* __restrict__ out, int N) {
    __shared__ float2 sm[8][32];
    int warp = threadIdx.x >> 5, lane = threadIdx.x & 31;
    int n = blockIdx.x * 8 + warp;
    if (n >= N) return;
    float adstv = g_adst2[n];
    int start = g_rowstart[n], end = g_rowstart[n + 1];
    bool act = lane < 20;
    float accx = 0.f, accy = 0.f, evs = 0.f;
    for (int i = start; i < end; i += 32) {
        int idx = i + lane;
        bool valid = idx < end;
        int s = valid ? g_adj[idx] : 0;
        float l = valid ? g_asrc2[s] : 0.f;
        float a = l + adstv; a = (a > 0.f) ? a : NEG * a;
        float e = valid ? __expf(a) : 0.f;
        evs += e;
        sm[warp][lane] = make_float2(__int_as_float(s), e);
        __syncwarp();
        int cnt = min(32, end - i);
        if (act) {
            #pragma unroll 8
            for (int j = 0; j < cnt; j++) {
                float2 t = sm[warp][j];
                int sj = __float_as_int(t.x);
                __half2 hv = *(const __half2*)&g_h2h[sj * H2STRIDE + 2 * lane];
                float2 fv = __half22float2(hv);
                accx += t.y * fv.x;
                accy += t.y * fv.y;
            }
        }
        __syncwarp();
    }
    #pragma unroll
    for (int o = 16; o >= 1; o >>= 1) evs += __shfl_xor_sync(0xffffffffu, evs, o);
    float inv = 1.f / (evs + 1e-16f);
    float v0 = act ? (accx * inv + b2[2 * lane])     : -INFINITY;
    float v1 = act ? (accy * inv + b2[2 * lane + 1]) : -INFINITY;
    float m = fmaxf(v0, v1);
    #pragma unroll
    for (int o = 16; o >= 1; o >>= 1) m = fmaxf(m, __shfl_xor_sync(0xffffffffu, m, o));
    float ssum = act ? (expf(v0 - m) + expf(v1 - m)) : 0.f;
    #pragma unroll
    for (int o = 16; o >= 1; o >>= 1) ssum += __shfl_xor_sync(0xffffffffu, ssum, o);
    float lse = logf(ssum);
    if (act) {
        out[n * C2 + 2 * lane]     = v0 - m - lse;
        out[n * C2 + 2 * lane + 1] = v1 - m - lse;
    }
}

// ---------------------------------------------------------------------------
extern "C" void kernel_launch(void* const* d_in, const int* in_sizes, int n_in,
                              void* d_out, int out_size) {
    const float* x   = (const float*)d_in[0];
    const int*   ei  = (const int*)d_in[1];
    const float* W1  = (const float*)d_in[2];
    const float* as1 = (const float*)d_in[3];
    const float* ad1 = (const float*)d_in[4];
    const float* b1  = (const float*)d_in[5];
    const float* W2  = (const float*)d_in[6];
    const float* as2 = (const float*)d_in[7];
    const float* ad2 = (const float*)d_in[8];
    const float* b2  = (const float*)d_in[9];
    float* out = (float*)d_out;

    int N  = in_sizes[0] / FIN;
    int E  = in_sizes[1] / 2;
    int vec = ((E & 3) == 0) ? 1 : 0;
    int eThreads = (E + 3) / 4;
    int scanBlocks = (N + 1023) / 1024;   // <= 128

    // One-time resources for fork-join capture (created on uncaptured
    // correctness call; no device memory involved).
    static cudaStream_t sB = nullptr;
    static cudaEvent_t evF = nullptr, evJ = nullptr;
    if (sB == nullptr) {
        cudaStreamCreateWithFlags(&sB, cudaStreamNonBlocking);
        cudaEventCreateWithFlags(&evF, cudaEventDisableTiming);
        cudaEventCreateWithFlags(&evJ, cudaEventDisableTiming);
    }

    // Fork: CSR build on sB concurrent with k1 GEMM on the main stream.
    cudaEventRecord(evF, 0);
    cudaStreamWaitEvent(sB, evF, 0);

    k_hist<<<(eThreads + 255) / 256, 256, 0, sB>>>(ei, E, vec);
    k_scan1<<<scanBlocks, 1024, 0, sB>>>(N);
    k1_gemm<<<(N + 127) / 128, 256>>>(x, W1, as1, ad1, N);    // main stream
    k_fill<<<(eThreads + 255) / 256, 256, 0, sB>>>(ei, E, vec);

    // Join.
    cudaEventRecord(evJ, sB);
    cudaStreamWaitEvent(0, evJ, 0);

    k2_gather<<<(N + 7) / 8, 256>>>(b1, N);
    k3_node<<<(N + 255) / 256, 256>>>(W2, as2, ad2, N);
    k45_gather_out<<<(N + 7) / 8, 256>>>(b2, out, N);
}